// round 11
// baseline (speedup 1.0000x reference)
#include <cuda_runtime.h>
#include <cuda_bf16.h>
#include <math.h>

#define N_NODES 4096
#define NFEAT   1024
#define NHID    128
#define NHEADS  8
#define NCLASS  64
#define NWORDS  (N_NODES / 32)
#define ALPHA_LRELU 0.2f

__device__ float g_Wh[NHEADS * N_NODES * NHID];
__device__ __nv_bfloat16 g_xhi[N_NODES * NFEAT];
__device__ __nv_bfloat16 g_xlo[N_NODES * NFEAT];
__device__ __nv_bfloat16 g_WThi[NHEADS * NHID * NFEAT];
__device__ __nv_bfloat16 g_WTlo[NHEADS * NHID * NFEAT];
__device__ __nv_bfloat16 g_WhT_hi[NHEADS * NHID * N_NODES];
__device__ __nv_bfloat16 g_WhT_lo[NHEADS * NHID * N_NODES];
__device__ float g_f1[NHEADS * N_NODES];
__device__ float g_f2[NHEADS * N_NODES];
__device__ float2 g_e1[NHEADS * N_NODES];
__device__ float2 g_e2[NHEADS * N_NODES];
__device__ float g_hcat[N_NODES * NHEADS * NHID];
__device__ float g_WhoP[4 * N_NODES * NCLASS];
__device__ float g_Who[N_NODES * NCLASS];
__device__ float g_g1[N_NODES];
__device__ float2 g_eo1[N_NODES];
__device__ float2 g_eo2[N_NODES];
__device__ unsigned g_adjbits[N_NODES * NWORDS];

typedef unsigned long long ull;

__device__ __forceinline__ ull pack2(float lo, float hi) {
    ull r; asm("mov.b64 %0,{%1,%2};" : "=l"(r) : "f"(lo), "f"(hi)); return r;
}
__device__ __forceinline__ float2 unpack2(ull v) {
    float2 f; asm("mov.b64 {%0,%1},%2;" : "=f"(f.x), "=f"(f.y) : "l"(v)); return f;
}
__device__ __forceinline__ ull fma2(ull a, ull b, ull c) {
    ull d; asm("fma.rn.f32x2 %0,%1,%2,%3;" : "=l"(d) : "l"(a), "l"(b), "l"(c)); return d;
}
__device__ __forceinline__ void cp16(void* dst, const void* src) {
    unsigned sa = (unsigned)__cvta_generic_to_shared(dst);
    asm volatile("cp.async.cg.shared.global [%0], [%1], 16;" :: "r"(sa), "l"(src));
}
#define CP_COMMIT() asm volatile("cp.async.commit_group;")
#define CP_WAIT0()  asm volatile("cp.async.wait_group 0;")
#define CP_WAIT1()  asm volatile("cp.async.wait_group 1;")

__device__ __forceinline__ void ldsm4(unsigned* r, unsigned a) {
    asm volatile("ldmatrix.sync.aligned.m8n8.x4.shared.b16 {%0,%1,%2,%3}, [%4];"
                 : "=r"(r[0]), "=r"(r[1]), "=r"(r[2]), "=r"(r[3]) : "r"(a));
}
__device__ __forceinline__ void mma16816(float* d, const unsigned* a, const unsigned* b) {
    asm volatile("mma.sync.aligned.m16n8k16.row.col.f32.bf16.bf16.f32 "
                 "{%0,%1,%2,%3}, {%4,%5,%6,%7}, {%8,%9}, {%0,%1,%2,%3};"
                 : "+f"(d[0]), "+f"(d[1]), "+f"(d[2]), "+f"(d[3])
                 : "r"(a[0]), "r"(a[1]), "r"(a[2]), "r"(a[3]), "r"(b[0]), "r"(b[1]));
}
__device__ __forceinline__ void bfsplit(float v, __nv_bfloat16& h, __nv_bfloat16& l) {
    h = __float2bfloat16(v);
    l = __float2bfloat16(v - __bfloat162float(h));
}

// 8-warp symmetric 3-term MMA core (used by wh_mma): A/B rows stride 144B.
__device__ __forceinline__ void mma_block(float acc[2][8][4], unsigned AHI, unsigned ALO,
                                          unsigned BHI, unsigned BLO, int mB, int nB, int lane) {
    #pragma unroll
    for (int kt = 0; kt < 4; kt++) {
        const unsigned ka = (kt * 16 + ((lane >> 4) * 8)) * 2;
        const unsigned kb = (kt * 16 + (((lane >> 3) & 1) * 8)) * 2;
        unsigned ah[2][4], al[2][4];
        #pragma unroll
        for (int mi = 0; mi < 2; mi++) {
            unsigned ao = (mB + mi * 16 + (lane & 15)) * 144 + ka;
            ldsm4(ah[mi], AHI + ao);
            ldsm4(al[mi], ALO + ao);
        }
        unsigned bh[4][4], bl[4][4];
        #pragma unroll
        for (int np = 0; np < 4; np++) {
            unsigned bo = (nB + np * 16 + (lane & 7) + ((lane >> 4) * 8)) * 144 + kb;
            ldsm4(bh[np], BHI + bo);
            ldsm4(bl[np], BLO + bo);
        }
        #pragma unroll
        for (int mi = 0; mi < 2; mi++)
            #pragma unroll
            for (int np = 0; np < 4; np++) {
                mma16816(acc[mi][np * 2],     ah[mi], &bh[np][0]);
                mma16816(acc[mi][np * 2],     ah[mi], &bl[np][0]);
                mma16816(acc[mi][np * 2],     al[mi], &bh[np][0]);
                mma16816(acc[mi][np * 2 + 1], ah[mi], &bh[np][2]);
                mma16816(acc[mi][np * 2 + 1], ah[mi], &bl[np][2]);
                mma16816(acc[mi][np * 2 + 1], al[mi], &bh[np][2]);
            }
    }
}

// K0: bit-pack adjacency
__global__ void bitpack_kernel(const int* __restrict__ adj) {
    int idx = blockIdx.x * 256 + threadIdx.x;
    int4 v = ((const int4*)adj)[idx];
    unsigned b = (v.x > 0 ? 1u : 0u) | (v.y > 0 ? 2u : 0u)
               | (v.z > 0 ? 4u : 0u) | (v.w > 0 ? 8u : 0u);
    b |= __shfl_xor_sync(~0u, b, 1) << 4;
    b |= __shfl_xor_sync(~0u, b, 2) << 8;
    b |= __shfl_xor_sync(~0u, b, 4) << 16;
    if ((threadIdx.x & 7) == 0) g_adjbits[idx >> 3] = b;
}

// K0b: x -> bf16 hi/lo
__global__ void xcvt_kernel(const float* __restrict__ x) {
    int i = blockIdx.x * 256 + threadIdx.x;
    float4 v = ((const float4*)x)[i];
    __nv_bfloat16 h[4], l[4];
    bfsplit(v.x, h[0], l[0]); bfsplit(v.y, h[1], l[1]);
    bfsplit(v.z, h[2], l[2]); bfsplit(v.w, h[3], l[3]);
    *(ull*)&g_xhi[i * 4] = *(ull*)h;
    *(ull*)&g_xlo[i * 4] = *(ull*)l;
}

// K0c: W -> WT bf16 hi/lo
__global__ void wcvt_kernel(const float* __restrict__ W) {
    int idx = blockIdx.x * 256 + threadIdx.x;
    int h = idx >> 17, rem = idx & 131071;
    int d = rem >> 10, k = rem & 1023;
    float v = W[h * (NFEAT * NHID) + k * NHID + d];
    __nv_bfloat16 hb, lb; bfsplit(v, hb, lb);
    g_WThi[idx] = hb; g_WTlo[idx] = lb;
}

// K1: Wh = x @ W via mma.sync bf16 3-term
#define WH_ST 73728
__global__ __launch_bounds__(256) void wh_mma() {
    extern __shared__ __align__(16) char smx[];
    const unsigned sb = (unsigned)__cvta_generic_to_shared(smx);
    const int tid = threadIdx.x, lane = tid & 31, w = tid >> 5;
    const int m0 = blockIdx.x * 128, h = blockIdx.y;
    const int mB = (w & 3) * 32, nB = (w >> 2) * 64;

    float acc[2][8][4];
    #pragma unroll
    for (int mi = 0; mi < 2; mi++)
        #pragma unroll
        for (int nt = 0; nt < 8; nt++)
            #pragma unroll
            for (int e = 0; e < 4; e++) acc[mi][nt][e] = 0.f;

    const __nv_bfloat16* WTh = g_WThi + (size_t)h * NHID * NFEAT;
    const __nv_bfloat16* WTl = g_WTlo + (size_t)h * NHID * NFEAT;

    #define WH_LD(tt, ss) { char* dst = smx + (ss) * WH_ST; size_t ko = (size_t)(tt) * 64; \
        _Pragma("unroll") \
        for (int q = 0; q < 4; q++) { \
            int idx = tid + q * 256; int row = idx >> 3, ch = idx & 7; \
            unsigned off = row * 144 + ch * 16; \
            cp16(dst + off,         g_xhi + (size_t)(m0 + row) * NFEAT + ko + ch * 8); \
            cp16(dst + 18432 + off, g_xlo + (size_t)(m0 + row) * NFEAT + ko + ch * 8); \
            cp16(dst + 36864 + off, WTh + (size_t)row * NFEAT + ko + ch * 8); \
            cp16(dst + 55296 + off, WTl + (size_t)row * NFEAT + ko + ch * 8); } }

    WH_LD(0, 0); CP_COMMIT();
    for (int t = 0; t < 16; t++) {
        const int s = t & 1;
        if (t + 1 < 16) { WH_LD(t + 1, (t + 1) & 1); CP_COMMIT(); CP_WAIT1(); }
        else CP_WAIT0();
        __syncthreads();
        unsigned base = sb + s * WH_ST;
        mma_block(acc, base, base + 18432, base + 36864, base + 55296, mB, nB, lane);
        __syncthreads();
    }
    #pragma unroll
    for (int mi = 0; mi < 2; mi++)
        #pragma unroll
        for (int eh = 0; eh < 2; eh++) {
            int row = mB + mi * 16 + (lane >> 2) + eh * 8;
            float* dst = g_Wh + ((size_t)h * N_NODES + m0 + row) * NHID + nB + (lane & 3) * 2;
            #pragma unroll
            for (int nt = 0; nt < 8; nt++)
                *(float2*)(dst + nt * 8) = make_float2(acc[mi][nt][eh * 2], acc[mi][nt][eh * 2 + 1]);
        }
}

// K1t: Wh -> WhT hi/lo (coalesced tile transpose)
__global__ __launch_bounds__(256) void whT_kernel() {
    __shared__ float tile[64][65];
    const int h = blockIdx.z, d0 = blockIdx.y * 64, n0 = blockIdx.x * 64;
    const int tid = threadIdx.x;
    #pragma unroll
    for (int q = 0; q < 16; q++) {
        int lin = tid + q * 256;
        int row = lin >> 6, col = lin & 63;
        tile[row][col] = g_Wh[((size_t)h * N_NODES + n0 + row) * NHID + d0 + col];
    }
    __syncthreads();
    #pragma unroll
    for (int q = 0; q < 8; q++) {
        int lin = tid + q * 256;
        int drow = lin >> 5, np = (lin & 31) * 2;
        float v0 = tile[np][drow], v1 = tile[np + 1][drow];
        __nv_bfloat16 h0, l0, h1, l1;
        bfsplit(v0, h0, l0); bfsplit(v1, h1, l1);
        unsigned hw = (unsigned)__bfloat16_as_ushort(h0) | ((unsigned)__bfloat16_as_ushort(h1) << 16);
        unsigned lw = (unsigned)__bfloat16_as_ushort(l0) | ((unsigned)__bfloat16_as_ushort(l1) << 16);
        size_t o = ((size_t)h * NHID + d0 + drow) * N_NODES + n0 + np;
        *(unsigned*)&g_WhT_hi[o] = hw;
        *(unsigned*)&g_WhT_lo[o] = lw;
    }
}

// K1b: f1/f2 + factored exps
__global__ void f12_kernel(const float* __restrict__ a1, const float* __restrict__ a2) {
    int gw = (blockIdx.x * blockDim.x + threadIdx.x) >> 5;
    int lane = threadIdx.x & 31;
    if (gw >= NHEADS * N_NODES) return;
    int h = gw >> 12;
    const float* wh = g_Wh + (size_t)gw * NHID;
    const float* A1 = a1 + h * NHID;
    const float* A2 = a2 + h * NHID;
    float s1 = 0.f, s2 = 0.f;
    #pragma unroll
    for (int d = lane; d < NHID; d += 32) {
        float v = wh[d];
        s1 += v * A1[d]; s2 += v * A2[d];
    }
    #pragma unroll
    for (int o = 16; o; o >>= 1) {
        s1 += __shfl_xor_sync(~0u, s1, o);
        s2 += __shfl_xor_sync(~0u, s2, o);
    }
    if (lane == 0) {
        g_f1[gw] = s1; g_f2[gw] = s2;
        g_e1[gw] = make_float2(__expf(s1), __expf(ALPHA_LRELU * s1));
        g_e2[gw] = make_float2(__expf(s2), __expf(ALPHA_LRELU * s2));
    }
}

// K2: attn layer-1 — WARP SPECIALIZED: warps 0-3 MMA (one per SMSP), warps 4-7 produce P.
#define OFF_WS  0
#define OFF_P   73728
#define OFF_LP  147456
#define SMEM_ATTN1 148480

__global__ __launch_bounds__(256) void gat_attn1() {
    extern __shared__ __align__(16) char smx[];
    const unsigned sb = (unsigned)__cvta_generic_to_shared(smx);
    const int tid = threadIdx.x, lane = tid & 31, w = tid >> 5;
    const int h = blockIdx.y, i0 = blockIdx.x * 128;
    const int hN = h * N_NODES;
    const bool is_mma = (w < 4);

    // producer state (warps 4-7): row = (w-4)*32 + lane
    const int pr = (w & 3) * 32 + lane, parow = i0 + pr;
    const float f1r = g_f1[hN + parow];
    const float2 e1 = g_e1[hN + parow];
    float lacc = 0.f;

    // consumer state (warps 0-3): rows mB..mB+31, all 128 cols
    const int mB = w * 32;
    float acc[2][16][4];
    if (is_mma) {
        #pragma unroll
        for (int mi = 0; mi < 2; mi++)
            #pragma unroll
            for (int nt = 0; nt < 16; nt++)
                #pragma unroll
                for (int e = 0; e < 4; e++) acc[mi][nt][e] = 0.f;
    }

    const __nv_bfloat16* WTh = g_WhT_hi + (size_t)h * NHID * N_NODES;
    const __nv_bfloat16* WTl = g_WhT_lo + (size_t)h * NHID * N_NODES;

    #define W_LD(tt, ss) { char* dst = smx + OFF_WS + (ss) * 36864; size_t so = (size_t)(tt) * 64; \
        _Pragma("unroll") \
        for (int q = 0; q < 4; q++) { \
            int idx = tid + q * 256; int d = idx >> 3, ch = idx & 7; \
            cp16(dst + d * 144 + ch * 16,         WTh + (size_t)d * N_NODES + so + ch * 8); \
            cp16(dst + 18432 + d * 144 + ch * 16, WTl + (size_t)d * N_NODES + so + ch * 8); } }

    // producer: full row (both 32-j halves) per tile
    #define P_GEN(tt, ss) { char* pstg = smx + OFF_P + (ss) * 36864; \
        _Pragma("unroll") \
        for (int jh = 0; jh < 2; jh++) { \
            unsigned word = g_adjbits[(size_t)parow * NWORDS + (tt) * 2 + jh]; \
            float f2v = g_f2[hN + (tt) * 64 + jh * 32 + lane]; \
            float2 e2v = g_e2[hN + (tt) * 64 + jh * 32 + lane]; \
            unsigned pbase = pr * 144 + jh * 64; \
            _Pragma("unroll") \
            for (int jq = 0; jq < 8; jq++) { \
                unsigned hv[2], lv[2]; \
                _Pragma("unroll") \
                for (int u = 0; u < 2; u++) { \
                    float p[2]; \
                    _Pragma("unroll") \
                    for (int vv = 0; vv < 2; vv++) { \
                        int j = jq * 4 + u * 2 + vv; \
                        float f2j = __shfl_sync(~0u, f2v, j); \
                        float ep  = __shfl_sync(~0u, e2v.x, j); \
                        float en  = __shfl_sync(~0u, e2v.y, j); \
                        float pv = (f1r + f2j > 0.f) ? e1.x * ep : e1.y * en; \
                        pv = ((word >> j) & 1u) ? pv : 0.f; \
                        lacc += pv; \
                        p[vv] = pv; \
                    } \
                    __nv_bfloat16 h0, l0, h1, l1; \
                    bfsplit(p[0], h0, l0); bfsplit(p[1], h1, l1); \
                    hv[u] = (unsigned)__bfloat16_as_ushort(h0) | ((unsigned)__bfloat16_as_ushort(h1) << 16); \
                    lv[u] = (unsigned)__bfloat16_as_ushort(l0) | ((unsigned)__bfloat16_as_ushort(l1) << 16); \
                } \
                ull hp; asm("mov.b64 %0,{%1,%2};" : "=l"(hp) : "r"(hv[0]), "r"(hv[1])); \
                ull lp; asm("mov.b64 %0,{%1,%2};" : "=l"(lp) : "r"(lv[0]), "r"(lv[1])); \
                *(ull*)(pstg + pbase + jq * 8) = hp; \
                *(ull*)(pstg + 18432 + pbase + jq * 8) = lp; \
            } } }

    W_LD(0, 0); CP_COMMIT();
    W_LD(1, 1); CP_COMMIT();
    if (!is_mma) P_GEN(0, 0);
    CP_WAIT1();
    __syncthreads();

    for (int t = 0; t < 64; t++) {
        const int s = t & 1;
        if (is_mma) {
            const unsigned PHI = sb + OFF_P + s * 36864, PLO = PHI + 18432;
            const unsigned BHI = sb + OFF_WS + s * 36864, BLO = BHI + 18432;
            #pragma unroll
            for (int kt = 0; kt < 4; kt++) {
                const unsigned ka = (kt * 16 + ((lane >> 4) * 8)) * 2;
                const unsigned kb = (kt * 16 + (((lane >> 3) & 1) * 8)) * 2;
                unsigned ah[2][4], al[2][4];
                #pragma unroll
                for (int mi = 0; mi < 2; mi++) {
                    unsigned ao = (mB + mi * 16 + (lane & 15)) * 144 + ka;
                    ldsm4(ah[mi], PHI + ao);
                    ldsm4(al[mi], PLO + ao);
                }
                #pragma unroll
                for (int np = 0; np < 8; np++) {
                    unsigned bo = (np * 16 + (lane & 7) + ((lane >> 4) * 8)) * 144 + kb;
                    unsigned bh[4], bl[4];
                    ldsm4(bh, BHI + bo);
                    ldsm4(bl, BLO + bo);
                    #pragma unroll
                    for (int mi = 0; mi < 2; mi++) {
                        mma16816(acc[mi][np * 2],     ah[mi], &bh[0]);
                        mma16816(acc[mi][np * 2],     ah[mi], &bl[0]);
                        mma16816(acc[mi][np * 2],     al[mi], &bh[0]);
                        mma16816(acc[mi][np * 2 + 1], ah[mi], &bh[2]);
                        mma16816(acc[mi][np * 2 + 1], ah[mi], &bl[2]);
                        mma16816(acc[mi][np * 2 + 1], al[mi], &bh[2]);
                    }
                }
            }
        } else {
            if (t + 1 < 64) P_GEN(t + 1, (t + 1) & 1);
        }
        __syncthreads();
        if (t + 2 < 64) { W_LD(t + 2, s); CP_COMMIT(); CP_WAIT1(); }
        else CP_WAIT0();
    }
    if (!is_mma) ((float*)(smx + OFF_LP))[pr] = lacc;
    __syncthreads();
    if (is_mma) {
        const float* LP = (const float*)(smx + OFF_LP);
        #pragma unroll
        for (int mi = 0; mi < 2; mi++)
            #pragma unroll
            for (int eh = 0; eh < 2; eh++) {
                int row = mB + mi * 16 + (lane >> 2) + eh * 8;
                float inv = 1.f / LP[row];
                float* dst = g_hcat + (size_t)(i0 + row) * (NHEADS * NHID) + h * NHID + (lane & 3) * 2;
                #pragma unroll
                for (int nt = 0; nt < 16; nt++) {
                    float v0 = acc[mi][nt][eh * 2] * inv;
                    float v1 = acc[mi][nt][eh * 2 + 1] * inv;
                    v0 = (v0 > 0.f) ? v0 : expm1f(v0);
                    v1 = (v1 > 0.f) ? v1 : expm1f(v1);
                    *(float2*)(dst + nt * 8) = make_float2(v0, v1);
                }
            }
    }
}

// K3: Who = hcat @ Wo (split-K=4, f32x2)
__global__ __launch_bounds__(256) void who_gemm(const float* __restrict__ Wo) {
    __shared__ float As[16][128];
    __shared__ float Bs[16][64];
    const int m0 = blockIdx.x * 128, kb = blockIdx.y;
    const int tid = threadIdx.x;
    const int tr = tid >> 4, tc = tid & 15;
    const int am = tid >> 1, ak = (tid & 1) * 8;
    const int bk = tid >> 4, bn = (tid & 15) * 4;

    ull acc[8][2];
    #pragma unroll
    for (int i = 0; i < 8; i++) { acc[i][0] = 0ull; acc[i][1] = 0ull; }
    const int kbeg = kb * 256, kend = kbeg + 256;
    for (int k0 = kbeg; k0 < kend; k0 += 16) {
        float4 a0 = *(const float4*)(g_hcat + (size_t)(m0 + am) * (NHEADS * NHID) + k0 + ak);
        float4 a1v = *(const float4*)(g_hcat + (size_t)(m0 + am) * (NHEADS * NHID) + k0 + ak + 4);
        As[ak + 0][am] = a0.x; As[ak + 1][am] = a0.y;
        As[ak + 2][am] = a0.z; As[ak + 3][am] = a0.w;
        As[ak + 4][am] = a1v.x; As[ak + 5][am] = a1v.y;
        As[ak + 6][am] = a1v.z; As[ak + 7][am] = a1v.w;
        *(float4*)&Bs[bk][bn] = *(const float4*)(Wo + (size_t)(k0 + bk) * NCLASS + bn);
        __syncthreads();
        #pragma unroll
        for (int k = 0; k < 16; k++) {
            float a[8];
            *(float4*)&a[0] = *(float4*)&As[k][tr * 8];
            *(float4*)&a[4] = *(float4*)&As[k][tr * 8 + 4];
            ulonglong2 b = *(ulonglong2*)&Bs[k][tc * 4];
            #pragma unroll
            for (int i = 0; i < 8; i++) {
                ull ap = pack2(a[i], a[i]);
                acc[i][0] = fma2(ap, b.x, acc[i][0]);
                acc[i][1] = fma2(ap, b.y, acc[i][1]);
            }
        }
        __syncthreads();
    }
    float* C = g_WhoP + (size_t)kb * N_NODES * NCLASS;
    #pragma unroll
    for (int i = 0; i < 8; i++) {
        ulonglong2 v; v.x = acc[i][0]; v.y = acc[i][1];
        *(ulonglong2*)(C + (size_t)(m0 + tr * 8 + i) * NCLASS + tc * 4) = v;
    }
}

// K3b: reduce split-K, g1/g2 exps
__global__ void g12_kernel(const float* __restrict__ ao1, const float* __restrict__ ao2) {
    int gw = (blockIdx.x * blockDim.x + threadIdx.x) >> 5;
    int lane = threadIdx.x & 31;
    if (gw >= N_NODES) return;
    size_t base = (size_t)gw * NCLASS;
    float v1 = 0.f, v2 = 0.f;
    #pragma unroll
    for (int kb = 0; kb < 4; kb++) {
        v1 += g_WhoP[(size_t)kb * N_NODES * NCLASS + base + lane];
        v2 += g_WhoP[(size_t)kb * N_NODES * NCLASS + base + lane + 32];
    }
    g_Who[base + lane] = v1;
    g_Who[base + lane + 32] = v2;
    float s1 = v1 * ao1[lane] + v2 * ao1[lane + 32];
    float s2 = v1 * ao2[lane] + v2 * ao2[lane + 32];
    #pragma unroll
    for (int o = 16; o; o >>= 1) {
        s1 += __shfl_xor_sync(~0u, s1, o);
        s2 += __shfl_xor_sync(~0u, s2, o);
    }
    if (lane == 0) {
        g_g1[gw] = s1;
        g_eo1[gw] = make_float2(__expf(s1), __expf(ALPHA_LRELU * s1));
        g_eo2[gw] = make_float2(__expf(s2), __expf(ALPHA_LRELU * s2));
    }
}

// K4: output attention — pipelined scalar (R8 version)
__global__ __launch_bounds__(256) void gat_attn2(float* __restrict__ out) {
    __shared__ float VS[2][64][NCLASS];
    __shared__ float P[2][32][65];
    __shared__ float l_s[32];
    const int i0 = blockIdx.x * 32;
    const int tid = threadIdx.x, lane = tid & 31, w = tid >> 5;

    float2 e1v[4]; float lacc[4];
    #pragma unroll
    for (int rr = 0; rr < 4; rr++) {
        e1v[rr] = g_eo1[i0 + w * 4 + rr];
        lacc[rr] = 0.f;
    }
    const int tr = tid >> 4, tc = tid & 15;
    ull O[2][2];
    O[0][0] = 0ull; O[0][1] = 0ull; O[1][0] = 0ull; O[1][1] = 0ull;

    #define VS_LD(tt, ss) { _Pragma("unroll") for (int q = 0; q < 4; q++) { \
        int idx = tid + q * 256; int row = idx >> 4, c = (idx & 15) * 4; \
        *(float4*)&VS[ss][row][c] = *(const float4*)(g_Who + (size_t)((tt) * 64 + row) * NCLASS + c); } }

    #define P_GEN2(tt, ss) { \
        float2 eo2a = g_eo2[(tt) * 64 + lane]; \
        float2 eo2b = g_eo2[(tt) * 64 + 32 + lane]; \
        _Pragma("unroll") for (int rr = 0; rr < 4; rr++) { \
            int rq = w * 4 + rr; \
            uint2 bw = *(const uint2*)&g_adjbits[(size_t)(i0 + rq) * NWORDS + (tt) * 2]; \
            float pr1 = e1v[rr].x * eo2a.x; \
            float pr2 = e1v[rr].x * eo2b.x; \
            float p1 = (pr1 > 1.f) ? pr1 : e1v[rr].y * eo2a.y; \
            float p2 = (pr2 > 1.f) ? pr2 : e1v[rr].y * eo2b.y; \
            p1 = ((bw.x >> lane) & 1u) ? p1 : 0.f; \
            p2 = ((bw.y >> lane) & 1u) ? p2 : 0.f; \
            P[ss][rq][lane] = p1; P[ss][rq][lane + 32] = p2; \
            lacc[rr] += p1 + p2; } }

    VS_LD(0, 0); P_GEN2(0, 0);
    __syncthreads();
    for (int t = 0; t < 64; t++) {
        const int s = t & 1;
        #pragma unroll 4
        for (int j = 0; j < 64; j++) {
            ulonglong2 wv = *(ulonglong2*)&VS[s][j][tc * 4];
            float pa = P[s][tr * 2][j], pb = P[s][tr * 2 + 1][j];
            ull ppa = pack2(pa, pa), ppb = pack2(pb, pb);
            O[0][0] = fma2(ppa, wv.x, O[0][0]);
            O[0][1] = fma2(ppa, wv.y, O[0][1]);
            O[1][0] = fma2(ppb, wv.x, O[1][0]);
            O[1][1] = fma2(ppb, wv.y, O[1][1]);
        }
        if (t + 1 < 64) { VS_LD(t + 1, (t + 1) & 1); P_GEN2(t + 1, (t + 1) & 1); }
        __syncthreads();
    }
    #pragma unroll
    for (int rr = 0; rr < 4; rr++) {
        float v = lacc[rr];
        #pragma unroll
        for (int o = 16; o; o >>= 1) v += __shfl_xor_sync(~0u, v, o);
        if (lane == 0) l_s[w * 4 + rr] = v;
    }
    __syncthreads();
    #pragma unroll
    for (int a = 0; a < 2; a++) {
        int rq = tr * 2 + a;
        float inv = 1.f / l_s[rq];
        float o[4];
        float2 u0 = unpack2(O[a][0]); o[0] = u0.x * inv; o[1] = u0.y * inv;
        float2 u1 = unpack2(O[a][1]); o[2] = u1.x * inv; o[3] = u1.y * inv;
        #pragma unroll
        for (int b = 0; b < 4; b++) o[b] = (o[b] > 0.f) ? o[b] : expm1f(o[b]);
        *(float4*)(out + (size_t)(i0 + rq) * NCLASS + tc * 4) = *(float4*)&o[0];
    }
}

// K5: log_softmax
__global__ void logsoftmax_kernel(float* __restrict__ out) {
    int gw = (blockIdx.x * blockDim.x + threadIdx.x) >> 5;
    int lane = threadIdx.x & 31;
    if (gw >= N_NODES) return;
    float* row = out + (size_t)gw * NCLASS;
    float v1 = row[lane], v2 = row[lane + 32];
    float m = fmaxf(v1, v2);
    #pragma unroll
    for (int o = 16; o; o >>= 1) m = fmaxf(m, __shfl_xor_sync(~0u, m, o));
    float s = __expf(v1 - m) + __expf(v2 - m);
    #pragma unroll
    for (int o = 16; o; o >>= 1) s += __shfl_xor_sync(~0u, s, o);
    float ls = m + logf(s);
    row[lane] = v1 - ls;
    row[lane + 32] = v2 - ls;
}

extern "C" void kernel_launch(void* const* d_in, const int* in_sizes, int n_in,
                              void* d_out, int out_size) {
    const float* x   = (const float*)d_in[0];
    const int*   adj = (const int*)  d_in[1];
    const float* W   = (const float*)d_in[2];
    const float* a1  = (const float*)d_in[3];
    const float* a2  = (const float*)d_in[4];
    const float* Wo  = (const float*)d_in[5];
    const float* ao1 = (const float*)d_in[6];
    const float* ao2 = (const float*)d_in[7];
    float* out = (float*)d_out;

    cudaFuncSetAttribute(gat_attn1, cudaFuncAttributeMaxDynamicSharedMemorySize, SMEM_ATTN1);
    cudaFuncSetAttribute(wh_mma, cudaFuncAttributeMaxDynamicSharedMemorySize, 2 * WH_ST);

    bitpack_kernel<<<(N_NODES * N_NODES / 4) / 256, 256>>>(adj);
    xcvt_kernel<<<(N_NODES * NFEAT / 4) / 256, 256>>>(x);
    wcvt_kernel<<<(NHEADS * NHID * NFEAT) / 256, 256>>>(W);
    wh_mma<<<dim3(N_NODES / 128, NHEADS), 256, 2 * WH_ST>>>();
    whT_kernel<<<dim3(N_NODES / 64, NHID / 64, NHEADS), 256>>>();
    f12_kernel<<<(NHEADS * N_NODES) / 8, 256>>>(a1, a2);
    gat_attn1<<<dim3(N_NODES / 128, NHEADS), 256, SMEM_ATTN1>>>();
    who_gemm<<<dim3(N_NODES / 128, 4), 256>>>(Wo);
    g12_kernel<<<N_NODES / 8, 256>>>(ao1, ao2);
    gat_attn2<<<N_NODES / 32, 256>>>(out);
    logsoftmax_kernel<<<N_NODES / 8, 256>>>(out);
}

// round 12
// speedup vs baseline: 1.0082x; 1.0082x over previous
#include <cuda_runtime.h>
#include <cuda_bf16.h>
#include <math.h>

#define N_NODES 4096
#define NFEAT   1024
#define NHID    128
#define NHEADS  8
#define NCLASS  64
#define NWORDS  (N_NODES / 32)
#define ALPHA_LRELU 0.2f

__device__ float g_Wh[NHEADS * N_NODES * NHID];
__device__ __nv_bfloat16 g_xhi[N_NODES * NFEAT];
__device__ __nv_bfloat16 g_xlo[N_NODES * NFEAT];
__device__ __nv_bfloat16 g_WThi[NHEADS * NHID * NFEAT];
__device__ __nv_bfloat16 g_WTlo[NHEADS * NHID * NFEAT];
__device__ __nv_bfloat16 g_WhT_hi[NHEADS * NHID * N_NODES];
__device__ __nv_bfloat16 g_WhT_lo[NHEADS * NHID * N_NODES];
__device__ float g_f1[NHEADS * N_NODES];
__device__ float g_f2[NHEADS * N_NODES];
__device__ float2 g_e1[NHEADS * N_NODES];
__device__ float2 g_e2[NHEADS * N_NODES];
__device__ float g_hcat[N_NODES * NHEADS * NHID];
__device__ float g_WhoP[4 * N_NODES * NCLASS];
__device__ float g_Who[N_NODES * NCLASS];
__device__ float g_g1[N_NODES];
__device__ float2 g_eo1[N_NODES];
__device__ float2 g_eo2[N_NODES];
__device__ unsigned g_adjbits[N_NODES * NWORDS];

typedef unsigned long long ull;

__device__ __forceinline__ ull pack2(float lo, float hi) {
    ull r; asm("mov.b64 %0,{%1,%2};" : "=l"(r) : "f"(lo), "f"(hi)); return r;
}
__device__ __forceinline__ float2 unpack2(ull v) {
    float2 f; asm("mov.b64 {%0,%1},%2;" : "=f"(f.x), "=f"(f.y) : "l"(v)); return f;
}
__device__ __forceinline__ ull fma2(ull a, ull b, ull c) {
    ull d; asm("fma.rn.f32x2 %0,%1,%2,%3;" : "=l"(d) : "l"(a), "l"(b), "l"(c)); return d;
}
__device__ __forceinline__ void cp16(void* dst, const void* src) {
    unsigned sa = (unsigned)__cvta_generic_to_shared(dst);
    asm volatile("cp.async.cg.shared.global [%0], [%1], 16;" :: "r"(sa), "l"(src));
}
#define CP_COMMIT() asm volatile("cp.async.commit_group;")
#define CP_WAIT0()  asm volatile("cp.async.wait_group 0;")
#define CP_WAIT1()  asm volatile("cp.async.wait_group 1;")

__device__ __forceinline__ void ldsm4(unsigned* r, unsigned a) {
    asm volatile("ldmatrix.sync.aligned.m8n8.x4.shared.b16 {%0,%1,%2,%3}, [%4];"
                 : "=r"(r[0]), "=r"(r[1]), "=r"(r[2]), "=r"(r[3]) : "r"(a));
}
__device__ __forceinline__ void mma16816(float* d, const unsigned* a, const unsigned* b) {
    asm volatile("mma.sync.aligned.m16n8k16.row.col.f32.bf16.bf16.f32 "
                 "{%0,%1,%2,%3}, {%4,%5,%6,%7}, {%8,%9}, {%0,%1,%2,%3};"
                 : "+f"(d[0]), "+f"(d[1]), "+f"(d[2]), "+f"(d[3])
                 : "r"(a[0]), "r"(a[1]), "r"(a[2]), "r"(a[3]), "r"(b[0]), "r"(b[1]));
}
__device__ __forceinline__ void bfsplit(float v, __nv_bfloat16& h, __nv_bfloat16& l) {
    h = __float2bfloat16(v);
    l = __float2bfloat16(v - __bfloat162float(h));
}

// 3-term MMA core, TERM-MAJOR: same-accumulator reuse distance = 16 mmas
// (breaks the HMMA RAW latency chains that capped tensor pipe at 50%).
// Per-accumulator term order preserved (hh, hl, lh) -> numerics unchanged.
__device__ __forceinline__ void mma_block(float acc[2][8][4], unsigned AHI, unsigned ALO,
                                          unsigned BHI, unsigned BLO, int mB, int nB, int lane) {
    #pragma unroll
    for (int kt = 0; kt < 4; kt++) {
        const unsigned ka = (kt * 16 + ((lane >> 4) * 8)) * 2;
        const unsigned kb = (kt * 16 + (((lane >> 3) & 1) * 8)) * 2;
        unsigned ah[2][4], al[2][4];
        #pragma unroll
        for (int mi = 0; mi < 2; mi++) {
            unsigned ao = (mB + mi * 16 + (lane & 15)) * 144 + ka;
            ldsm4(ah[mi], AHI + ao);
            ldsm4(al[mi], ALO + ao);
        }
        unsigned bh[4][4], bl[4][4];
        #pragma unroll
        for (int np = 0; np < 4; np++) {
            unsigned bo = (nB + np * 16 + (lane & 7) + ((lane >> 4) * 8)) * 144 + kb;
            ldsm4(bh[np], BHI + bo);
            ldsm4(bl[np], BLO + bo);
        }
        // pass 1: hi*hi over all 16 accumulators
        #pragma unroll
        for (int mi = 0; mi < 2; mi++)
            #pragma unroll
            for (int np = 0; np < 4; np++) {
                mma16816(acc[mi][np * 2],     ah[mi], &bh[np][0]);
                mma16816(acc[mi][np * 2 + 1], ah[mi], &bh[np][2]);
            }
        // pass 2: hi*lo
        #pragma unroll
        for (int mi = 0; mi < 2; mi++)
            #pragma unroll
            for (int np = 0; np < 4; np++) {
                mma16816(acc[mi][np * 2],     ah[mi], &bl[np][0]);
                mma16816(acc[mi][np * 2 + 1], ah[mi], &bl[np][2]);
            }
        // pass 3: lo*hi
        #pragma unroll
        for (int mi = 0; mi < 2; mi++)
            #pragma unroll
            for (int np = 0; np < 4; np++) {
                mma16816(acc[mi][np * 2],     al[mi], &bh[np][0]);
                mma16816(acc[mi][np * 2 + 1], al[mi], &bh[np][2]);
            }
    }
}

// K0: bit-pack adjacency
__global__ void bitpack_kernel(const int* __restrict__ adj) {
    int idx = blockIdx.x * 256 + threadIdx.x;
    int4 v = ((const int4*)adj)[idx];
    unsigned b = (v.x > 0 ? 1u : 0u) | (v.y > 0 ? 2u : 0u)
               | (v.z > 0 ? 4u : 0u) | (v.w > 0 ? 8u : 0u);
    b |= __shfl_xor_sync(~0u, b, 1) << 4;
    b |= __shfl_xor_sync(~0u, b, 2) << 8;
    b |= __shfl_xor_sync(~0u, b, 4) << 16;
    if ((threadIdx.x & 7) == 0) g_adjbits[idx >> 3] = b;
}

// K0b: x -> bf16 hi/lo
__global__ void xcvt_kernel(const float* __restrict__ x) {
    int i = blockIdx.x * 256 + threadIdx.x;
    float4 v = ((const float4*)x)[i];
    __nv_bfloat16 h[4], l[4];
    bfsplit(v.x, h[0], l[0]); bfsplit(v.y, h[1], l[1]);
    bfsplit(v.z, h[2], l[2]); bfsplit(v.w, h[3], l[3]);
    *(ull*)&g_xhi[i * 4] = *(ull*)h;
    *(ull*)&g_xlo[i * 4] = *(ull*)l;
}

// K0c: W -> WT bf16 hi/lo
__global__ void wcvt_kernel(const float* __restrict__ W) {
    int idx = blockIdx.x * 256 + threadIdx.x;
    int h = idx >> 17, rem = idx & 131071;
    int d = rem >> 10, k = rem & 1023;
    float v = W[h * (NFEAT * NHID) + k * NHID + d];
    __nv_bfloat16 hb, lb; bfsplit(v, hb, lb);
    g_WThi[idx] = hb; g_WTlo[idx] = lb;
}

// K1: Wh = x @ W via mma.sync bf16 3-term
#define WH_ST 73728
__global__ __launch_bounds__(256) void wh_mma() {
    extern __shared__ __align__(16) char smx[];
    const unsigned sb = (unsigned)__cvta_generic_to_shared(smx);
    const int tid = threadIdx.x, lane = tid & 31, w = tid >> 5;
    const int m0 = blockIdx.x * 128, h = blockIdx.y;
    const int mB = (w & 3) * 32, nB = (w >> 2) * 64;

    float acc[2][8][4];
    #pragma unroll
    for (int mi = 0; mi < 2; mi++)
        #pragma unroll
        for (int nt = 0; nt < 8; nt++)
            #pragma unroll
            for (int e = 0; e < 4; e++) acc[mi][nt][e] = 0.f;

    const __nv_bfloat16* WTh = g_WThi + (size_t)h * NHID * NFEAT;
    const __nv_bfloat16* WTl = g_WTlo + (size_t)h * NHID * NFEAT;

    #define WH_LD(tt, ss) { char* dst = smx + (ss) * WH_ST; size_t ko = (size_t)(tt) * 64; \
        _Pragma("unroll") \
        for (int q = 0; q < 4; q++) { \
            int idx = tid + q * 256; int row = idx >> 3, ch = idx & 7; \
            unsigned off = row * 144 + ch * 16; \
            cp16(dst + off,         g_xhi + (size_t)(m0 + row) * NFEAT + ko + ch * 8); \
            cp16(dst + 18432 + off, g_xlo + (size_t)(m0 + row) * NFEAT + ko + ch * 8); \
            cp16(dst + 36864 + off, WTh + (size_t)row * NFEAT + ko + ch * 8); \
            cp16(dst + 55296 + off, WTl + (size_t)row * NFEAT + ko + ch * 8); } }

    WH_LD(0, 0); CP_COMMIT();
    for (int t = 0; t < 16; t++) {
        const int s = t & 1;
        if (t + 1 < 16) { WH_LD(t + 1, (t + 1) & 1); CP_COMMIT(); CP_WAIT1(); }
        else CP_WAIT0();
        __syncthreads();
        unsigned base = sb + s * WH_ST;
        mma_block(acc, base, base + 18432, base + 36864, base + 55296, mB, nB, lane);
        __syncthreads();
    }
    #pragma unroll
    for (int mi = 0; mi < 2; mi++)
        #pragma unroll
        for (int eh = 0; eh < 2; eh++) {
            int row = mB + mi * 16 + (lane >> 2) + eh * 8;
            float* dst = g_Wh + ((size_t)h * N_NODES + m0 + row) * NHID + nB + (lane & 3) * 2;
            #pragma unroll
            for (int nt = 0; nt < 8; nt++)
                *(float2*)(dst + nt * 8) = make_float2(acc[mi][nt][eh * 2], acc[mi][nt][eh * 2 + 1]);
        }
}

// K1t: Wh -> WhT hi/lo (coalesced tile transpose)
__global__ __launch_bounds__(256) void whT_kernel() {
    __shared__ float tile[64][65];
    const int h = blockIdx.z, d0 = blockIdx.y * 64, n0 = blockIdx.x * 64;
    const int tid = threadIdx.x;
    #pragma unroll
    for (int q = 0; q < 16; q++) {
        int lin = tid + q * 256;
        int row = lin >> 6, col = lin & 63;
        tile[row][col] = g_Wh[((size_t)h * N_NODES + n0 + row) * NHID + d0 + col];
    }
    __syncthreads();
    #pragma unroll
    for (int q = 0; q < 8; q++) {
        int lin = tid + q * 256;
        int drow = lin >> 5, np = (lin & 31) * 2;
        float v0 = tile[np][drow], v1 = tile[np + 1][drow];
        __nv_bfloat16 h0, l0, h1, l1;
        bfsplit(v0, h0, l0); bfsplit(v1, h1, l1);
        unsigned hw = (unsigned)__bfloat16_as_ushort(h0) | ((unsigned)__bfloat16_as_ushort(h1) << 16);
        unsigned lw = (unsigned)__bfloat16_as_ushort(l0) | ((unsigned)__bfloat16_as_ushort(l1) << 16);
        size_t o = ((size_t)h * NHID + d0 + drow) * N_NODES + n0 + np;
        *(unsigned*)&g_WhT_hi[o] = hw;
        *(unsigned*)&g_WhT_lo[o] = lw;
    }
}

// K1b: f1/f2 + factored exps
__global__ void f12_kernel(const float* __restrict__ a1, const float* __restrict__ a2) {
    int gw = (blockIdx.x * blockDim.x + threadIdx.x) >> 5;
    int lane = threadIdx.x & 31;
    if (gw >= NHEADS * N_NODES) return;
    int h = gw >> 12;
    const float* wh = g_Wh + (size_t)gw * NHID;
    const float* A1 = a1 + h * NHID;
    const float* A2 = a2 + h * NHID;
    float s1 = 0.f, s2 = 0.f;
    #pragma unroll
    for (int d = lane; d < NHID; d += 32) {
        float v = wh[d];
        s1 += v * A1[d]; s2 += v * A2[d];
    }
    #pragma unroll
    for (int o = 16; o; o >>= 1) {
        s1 += __shfl_xor_sync(~0u, s1, o);
        s2 += __shfl_xor_sync(~0u, s2, o);
    }
    if (lane == 0) {
        g_f1[gw] = s1; g_f2[gw] = s2;
        g_e1[gw] = make_float2(__expf(s1), __expf(ALPHA_LRELU * s1));
        g_e2[gw] = make_float2(__expf(s2), __expf(ALPHA_LRELU * s2));
    }
}

// K2: attn layer-1 — symmetric pipelined (R9) with term-major mma_block
#define OFF_WS  0
#define OFF_P   73728
#define OFF_LP  147456
#define SMEM_ATTN1 148480

__global__ __launch_bounds__(256) void gat_attn1() {
    extern __shared__ __align__(16) char smx[];
    const unsigned sb = (unsigned)__cvta_generic_to_shared(smx);
    const int tid = threadIdx.x, lane = tid & 31, w = tid >> 5;
    const int h = blockIdx.y, i0 = blockIdx.x * 128;
    const int hN = h * N_NODES;

    const int rg = w & 3, jh = w >> 2;
    const int r = rg * 32 + lane, arow = i0 + r;
    const float f1r = g_f1[hN + arow];
    const float2 e1 = g_e1[hN + arow];
    float lacc = 0.f;

    const int mB = (w & 3) * 32, nB = (w >> 2) * 64;
    float acc[2][8][4];
    #pragma unroll
    for (int mi = 0; mi < 2; mi++)
        #pragma unroll
        for (int nt = 0; nt < 8; nt++)
            #pragma unroll
            for (int e = 0; e < 4; e++) acc[mi][nt][e] = 0.f;

    const __nv_bfloat16* WTh = g_WhT_hi + (size_t)h * NHID * N_NODES;
    const __nv_bfloat16* WTl = g_WhT_lo + (size_t)h * NHID * N_NODES;

    #define W_LD(tt, ss) { char* dst = smx + OFF_WS + (ss) * 36864; size_t so = (size_t)(tt) * 64; \
        _Pragma("unroll") \
        for (int q = 0; q < 4; q++) { \
            int idx = tid + q * 256; int d = idx >> 3, ch = idx & 7; \
            cp16(dst + d * 144 + ch * 16,         WTh + (size_t)d * N_NODES + so + ch * 8); \
            cp16(dst + 18432 + d * 144 + ch * 16, WTl + (size_t)d * N_NODES + so + ch * 8); } }

    #define P_GEN(tt, ss) { char* pstg = smx + OFF_P + (ss) * 36864; \
        unsigned word = g_adjbits[(size_t)arow * NWORDS + (tt) * 2 + jh]; \
        float f2v = g_f2[hN + (tt) * 64 + jh * 32 + lane]; \
        float2 e2v = g_e2[hN + (tt) * 64 + jh * 32 + lane]; \
        unsigned pbase = r * 144 + jh * 64; \
        _Pragma("unroll") \
        for (int jq = 0; jq < 8; jq++) { \
            unsigned hv[2], lv[2]; \
            _Pragma("unroll") \
            for (int u = 0; u < 2; u++) { \
                float p[2]; \
                _Pragma("unroll") \
                for (int vv = 0; vv < 2; vv++) { \
                    int j = jq * 4 + u * 2 + vv; \
                    float f2j = __shfl_sync(~0u, f2v, j); \
                    float ep  = __shfl_sync(~0u, e2v.x, j); \
                    float en  = __shfl_sync(~0u, e2v.y, j); \
                    float pv = (f1r + f2j > 0.f) ? e1.x * ep : e1.y * en; \
                    pv = ((word >> j) & 1u) ? pv : 0.f; \
                    lacc += pv; \
                    p[vv] = pv; \
                } \
                __nv_bfloat16 h0, l0, h1, l1; \
                bfsplit(p[0], h0, l0); bfsplit(p[1], h1, l1); \
                hv[u] = (unsigned)__bfloat16_as_ushort(h0) | ((unsigned)__bfloat16_as_ushort(h1) << 16); \
                lv[u] = (unsigned)__bfloat16_as_ushort(l0) | ((unsigned)__bfloat16_as_ushort(l1) << 16); \
            } \
            ull hp; asm("mov.b64 %0,{%1,%2};" : "=l"(hp) : "r"(hv[0]), "r"(hv[1])); \
            ull lp; asm("mov.b64 %0,{%1,%2};" : "=l"(lp) : "r"(lv[0]), "r"(lv[1])); \
            *(ull*)(pstg + pbase + jq * 8) = hp; \
            *(ull*)(pstg + 18432 + pbase + jq * 8) = lp; \
        } }

    W_LD(0, 0); CP_COMMIT();
    W_LD(1, 1); CP_COMMIT();
    P_GEN(0, 0);
    CP_WAIT1();
    __syncthreads();

    for (int t = 0; t < 64; t++) {
        const int s = t & 1;
        unsigned wb = sb + OFF_WS + s * 36864;
        unsigned pb = sb + OFF_P + s * 36864;
        mma_block(acc, pb, pb + 18432, wb, wb + 18432, mB, nB, lane);
        if (t + 1 < 64) P_GEN(t + 1, (t + 1) & 1);
        __syncthreads();
        if (t + 2 < 64) { W_LD(t + 2, s); CP_COMMIT(); CP_WAIT1(); }
        else CP_WAIT0();
    }
    ((float*)(smx + OFF_LP))[jh * 128 + r] = lacc;
    __syncthreads();
    {
        const float* LP = (const float*)(smx + OFF_LP);
        #pragma unroll
        for (int mi = 0; mi < 2; mi++)
            #pragma unroll
            for (int eh = 0; eh < 2; eh++) {
                int row = mB + mi * 16 + (lane >> 2) + eh * 8;
                float inv = 1.f / (LP[row] + LP[128 + row]);
                float* dst = g_hcat + (size_t)(i0 + row) * (NHEADS * NHID) + h * NHID + nB + (lane & 3) * 2;
                #pragma unroll
                for (int nt = 0; nt < 8; nt++) {
                    float v0 = acc[mi][nt][eh * 2] * inv;
                    float v1 = acc[mi][nt][eh * 2 + 1] * inv;
                    v0 = (v0 > 0.f) ? v0 : expm1f(v0);
                    v1 = (v1 > 0.f) ? v1 : expm1f(v1);
                    *(float2*)(dst + nt * 8) = make_float2(v0, v1);
                }
            }
    }
}

// K3: Who = hcat @ Wo (split-K=4, f32x2)
__global__ __launch_bounds__(256) void who_gemm(const float* __restrict__ Wo) {
    __shared__ float As[16][128];
    __shared__ float Bs[16][64];
    const int m0 = blockIdx.x * 128, kb = blockIdx.y;
    const int tid = threadIdx.x;
    const int tr = tid >> 4, tc = tid & 15;
    const int am = tid >> 1, ak = (tid & 1) * 8;
    const int bk = tid >> 4, bn = (tid & 15) * 4;

    ull acc[8][2];
    #pragma unroll
    for (int i = 0; i < 8; i++) { acc[i][0] = 0ull; acc[i][1] = 0ull; }
    const int kbeg = kb * 256, kend = kbeg + 256;
    for (int k0 = kbeg; k0 < kend; k0 += 16) {
        float4 a0 = *(const float4*)(g_hcat + (size_t)(m0 + am) * (NHEADS * NHID) + k0 + ak);
        float4 a1v = *(const float4*)(g_hcat + (size_t)(m0 + am) * (NHEADS * NHID) + k0 + ak + 4);
        As[ak + 0][am] = a0.x; As[ak + 1][am] = a0.y;
        As[ak + 2][am] = a0.z; As[ak + 3][am] = a0.w;
        As[ak + 4][am] = a1v.x; As[ak + 5][am] = a1v.y;
        As[ak + 6][am] = a1v.z; As[ak + 7][am] = a1v.w;
        *(float4*)&Bs[bk][bn] = *(const float4*)(Wo + (size_t)(k0 + bk) * NCLASS + bn);
        __syncthreads();
        #pragma unroll
        for (int k = 0; k < 16; k++) {
            float a[8];
            *(float4*)&a[0] = *(float4*)&As[k][tr * 8];
            *(float4*)&a[4] = *(float4*)&As[k][tr * 8 + 4];
            ulonglong2 b = *(ulonglong2*)&Bs[k][tc * 4];
            #pragma unroll
            for (int i = 0; i < 8; i++) {
                ull ap = pack2(a[i], a[i]);
                acc[i][0] = fma2(ap, b.x, acc[i][0]);
                acc[i][1] = fma2(ap, b.y, acc[i][1]);
            }
        }
        __syncthreads();
    }
    float* C = g_WhoP + (size_t)kb * N_NODES * NCLASS;
    #pragma unroll
    for (int i = 0; i < 8; i++) {
        ulonglong2 v; v.x = acc[i][0]; v.y = acc[i][1];
        *(ulonglong2*)(C + (size_t)(m0 + tr * 8 + i) * NCLASS + tc * 4) = v;
    }
}

// K3b: reduce split-K, g1/g2 exps
__global__ void g12_kernel(const float* __restrict__ ao1, const float* __restrict__ ao2) {
    int gw = (blockIdx.x * blockDim.x + threadIdx.x) >> 5;
    int lane = threadIdx.x & 31;
    if (gw >= N_NODES) return;
    size_t base = (size_t)gw * NCLASS;
    float v1 = 0.f, v2 = 0.f;
    #pragma unroll
    for (int kb = 0; kb < 4; kb++) {
        v1 += g_WhoP[(size_t)kb * N_NODES * NCLASS + base + lane];
        v2 += g_WhoP[(size_t)kb * N_NODES * NCLASS + base + lane + 32];
    }
    g_Who[base + lane] = v1;
    g_Who[base + lane + 32] = v2;
    float s1 = v1 * ao1[lane] + v2 * ao1[lane + 32];
    float s2 = v1 * ao2[lane] + v2 * ao2[lane + 32];
    #pragma unroll
    for (int o = 16; o; o >>= 1) {
        s1 += __shfl_xor_sync(~0u, s1, o);
        s2 += __shfl_xor_sync(~0u, s2, o);
    }
    if (lane == 0) {
        g_g1[gw] = s1;
        g_eo1[gw] = make_float2(__expf(s1), __expf(ALPHA_LRELU * s1));
        g_eo2[gw] = make_float2(__expf(s2), __expf(ALPHA_LRELU * s2));
    }
}

// K4: output attention — pipelined scalar
__global__ __launch_bounds__(256) void gat_attn2(float* __restrict__ out) {
    __shared__ float VS[2][64][NCLASS];
    __shared__ float P[2][32][65];
    __shared__ float l_s[32];
    const int i0 = blockIdx.x * 32;
    const int tid = threadIdx.x, lane = tid & 31, w = tid >> 5;

    float2 e1v[4]; float lacc[4];
    #pragma unroll
    for (int rr = 0; rr < 4; rr++) {
        e1v[rr] = g_eo1[i0 + w * 4 + rr];
        lacc[rr] = 0.f;
    }
    const int tr = tid >> 4, tc = tid & 15;
    ull O[2][2];
    O[0][0] = 0ull; O[0][1] = 0ull; O[1][0] = 0ull; O[1][1] = 0ull;

    #define VS_LD(tt, ss) { _Pragma("unroll") for (int q = 0; q < 4; q++) { \
        int idx = tid + q * 256; int row = idx >> 4, c = (idx & 15) * 4; \
        *(float4*)&VS[ss][row][c] = *(const float4*)(g_Who + (size_t)((tt) * 64 + row) * NCLASS + c); } }

    #define P_GEN2(tt, ss) { \
        float2 eo2a = g_eo2[(tt) * 64 + lane]; \
        float2 eo2b = g_eo2[(tt) * 64 + 32 + lane]; \
        _Pragma("unroll") for (int rr = 0; rr < 4; rr++) { \
            int rq = w * 4 + rr; \
            uint2 bw = *(const uint2*)&g_adjbits[(size_t)(i0 + rq) * NWORDS + (tt) * 2]; \
            float pr1 = e1v[rr].x * eo2a.x; \
            float pr2 = e1v[rr].x * eo2b.x; \
            float p1 = (pr1 > 1.f) ? pr1 : e1v[rr].y * eo2a.y; \
            float p2 = (pr2 > 1.f) ? pr2 : e1v[rr].y * eo2b.y; \
            p1 = ((bw.x >> lane) & 1u) ? p1 : 0.f; \
            p2 = ((bw.y >> lane) & 1u) ? p2 : 0.f; \
            P[ss][rq][lane] = p1; P[ss][rq][lane + 32] = p2; \
            lacc[rr] += p1 + p2; } }

    VS_LD(0, 0); P_GEN2(0, 0);
    __syncthreads();
    for (int t = 0; t < 64; t++) {
        const int s = t & 1;
        #pragma unroll 4
        for (int j = 0; j < 64; j++) {
            ulonglong2 wv = *(ulonglong2*)&VS[s][j][tc * 4];
            float pa = P[s][tr * 2][j], pb = P[s][tr * 2 + 1][j];
            ull ppa = pack2(pa, pa), ppb = pack2(pb, pb);
            O[0][0] = fma2(ppa, wv.x, O[0][0]);
            O[0][1] = fma2(ppa, wv.y, O[0][1]);
            O[1][0] = fma2(ppb, wv.x, O[1][0]);
            O[1][1] = fma2(ppb, wv.y, O[1][1]);
        }
        if (t + 1 < 64) { VS_LD(t + 1, (t + 1) & 1); P_GEN2(t + 1, (t + 1) & 1); }
        __syncthreads();
    }
    #pragma unroll
    for (int rr = 0; rr < 4; rr++) {
        float v = lacc[rr];
        #pragma unroll
        for (int o = 16; o; o >>= 1) v += __shfl_xor_sync(~0u, v, o);
        if (lane == 0) l_s[w * 4 + rr] = v;
    }
    __syncthreads();
    #pragma unroll
    for (int a = 0; a < 2; a++) {
        int rq = tr * 2 + a;
        float inv = 1.f / l_s[rq];
        float o[4];
        float2 u0 = unpack2(O[a][0]); o[0] = u0.x * inv; o[1] = u0.y * inv;
        float2 u1 = unpack2(O[a][1]); o[2] = u1.x * inv; o[3] = u1.y * inv;
        #pragma unroll
        for (int b = 0; b < 4; b++) o[b] = (o[b] > 0.f) ? o[b] : expm1f(o[b]);
        *(float4*)(out + (size_t)(i0 + rq) * NCLASS + tc * 4) = *(float4*)&o[0];
    }
}

// K5: log_softmax
__global__ void logsoftmax_kernel(float* __restrict__ out) {
    int gw = (blockIdx.x * blockDim.x + threadIdx.x) >> 5;
    int lane = threadIdx.x & 31;
    if (gw >= N_NODES) return;
    float* row = out + (size_t)gw * NCLASS;
    float v1 = row[lane], v2 = row[lane + 32];
    float m = fmaxf(v1, v2);
    #pragma unroll
    for (int o = 16; o; o >>= 1) m = fmaxf(m, __shfl_xor_sync(~0u, m, o));
    float s = __expf(v1 - m) + __expf(v2 - m);
    #pragma unroll
    for (int o = 16; o; o >>= 1) s += __shfl_xor_sync(~0u, s, o);
    float ls = m + logf(s);
    row[lane] = v1 - ls;
    row[lane + 32] = v2 - ls;
}

extern "C" void kernel_launch(void* const* d_in, const int* in_sizes, int n_in,
                              void* d_out, int out_size) {
    const float* x   = (const float*)d_in[0];
    const int*   adj = (const int*)  d_in[1];
    const float* W   = (const float*)d_in[2];
    const float* a1  = (const float*)d_in[3];
    const float* a2  = (const float*)d_in[4];
    const float* Wo  = (const float*)d_in[5];
    const float* ao1 = (const float*)d_in[6];
    const float* ao2 = (const float*)d_in[7];
    float* out = (float*)d_out;

    cudaFuncSetAttribute(gat_attn1, cudaFuncAttributeMaxDynamicSharedMemorySize, SMEM_ATTN1);
    cudaFuncSetAttribute(wh_mma, cudaFuncAttributeMaxDynamicSharedMemorySize, 2 * WH_ST);

    bitpack_kernel<<<(N_NODES * N_NODES / 4) / 256, 256>>>(adj);
    xcvt_kernel<<<(N_NODES * NFEAT / 4) / 256, 256>>>(x);
    wcvt_kernel<<<(NHEADS * NHID * NFEAT) / 256, 256>>>(W);
    wh_mma<<<dim3(N_NODES / 128, NHEADS), 256, 2 * WH_ST>>>();
    whT_kernel<<<dim3(N_NODES / 64, NHID / 64, NHEADS), 256>>>();
    f12_kernel<<<(NHEADS * N_NODES) / 8, 256>>>(a1, a2);
    gat_attn1<<<dim3(N_NODES / 128, NHEADS), 256, SMEM_ATTN1>>>();
    who_gemm<<<dim3(N_NODES / 128, 4), 256>>>(Wo);
    g12_kernel<<<N_NODES / 8, 256>>>(ao1, ao2);
    gat_attn2<<<N_NODES / 32, 256>>>(out);
    logsoftmax_kernel<<<N_NODES / 8, 256>>>(out);
}

// round 13
// speedup vs baseline: 1.1069x; 1.0980x over previous
#include <cuda_runtime.h>
#include <cuda_bf16.h>
#include <math.h>

#define N_NODES 4096
#define NFEAT   1024
#define NHID    128
#define NHEADS  8
#define NCLASS  64
#define NWORDS  (N_NODES / 32)
#define ALPHA_LRELU 0.2f

__device__ float g_Wh[NHEADS * N_NODES * NHID];
__device__ __nv_bfloat16 g_xhi[N_NODES * NFEAT];
__device__ __nv_bfloat16 g_xlo[N_NODES * NFEAT];
__device__ __nv_bfloat16 g_WThi[NHEADS * NHID * NFEAT];
__device__ __nv_bfloat16 g_WTlo[NHEADS * NHID * NFEAT];
__device__ __nv_bfloat16 g_WhT_hi[NHEADS * NHID * N_NODES];
__device__ __nv_bfloat16 g_WhT_lo[NHEADS * NHID * N_NODES];
__device__ float g_f1[NHEADS * N_NODES];
__device__ float g_f2[NHEADS * N_NODES];
__device__ float2 g_e1[NHEADS * N_NODES];
__device__ float2 g_e2[NHEADS * N_NODES];
__device__ float g_hcat[N_NODES * NHEADS * NHID];
__device__ float g_WhoP[4 * N_NODES * NCLASS];
__device__ float g_Who[N_NODES * NCLASS];
__device__ float g_g1[N_NODES];
__device__ float2 g_eo1[N_NODES];
__device__ float2 g_eo2[N_NODES];
__device__ unsigned g_adjbits[N_NODES * NWORDS];

typedef unsigned long long ull;

__device__ __forceinline__ ull pack2(float lo, float hi) {
    ull r; asm("mov.b64 %0,{%1,%2};" : "=l"(r) : "f"(lo), "f"(hi)); return r;
}
__device__ __forceinline__ float2 unpack2(ull v) {
    float2 f; asm("mov.b64 {%0,%1},%2;" : "=f"(f.x), "=f"(f.y) : "l"(v)); return f;
}
__device__ __forceinline__ ull fma2(ull a, ull b, ull c) {
    ull d; asm("fma.rn.f32x2 %0,%1,%2,%3;" : "=l"(d) : "l"(a), "l"(b), "l"(c)); return d;
}
__device__ __forceinline__ void cp16(void* dst, const void* src) {
    unsigned sa = (unsigned)__cvta_generic_to_shared(dst);
    asm volatile("cp.async.cg.shared.global [%0], [%1], 16;" :: "r"(sa), "l"(src));
}
#define CP_COMMIT() asm volatile("cp.async.commit_group;")
#define CP_WAIT0()  asm volatile("cp.async.wait_group 0;")

__device__ __forceinline__ void ldsm4(unsigned* r, unsigned a) {
    asm volatile("ldmatrix.sync.aligned.m8n8.x4.shared.b16 {%0,%1,%2,%3}, [%4];"
                 : "=r"(r[0]), "=r"(r[1]), "=r"(r[2]), "=r"(r[3]) : "r"(a));
}
__device__ __forceinline__ void mma16816(float* d, const unsigned* a, const unsigned* b) {
    asm volatile("mma.sync.aligned.m16n8k16.row.col.f32.bf16.bf16.f32 "
                 "{%0,%1,%2,%3}, {%4,%5,%6,%7}, {%8,%9}, {%0,%1,%2,%3};"
                 : "+f"(d[0]), "+f"(d[1]), "+f"(d[2]), "+f"(d[3])
                 : "r"(a[0]), "r"(a[1]), "r"(a[2]), "r"(a[3]), "r"(b[0]), "r"(b[1]));
}
__device__ __forceinline__ void bfsplit(float v, __nv_bfloat16& h, __nv_bfloat16& l) {
    h = __float2bfloat16(v);
    l = __float2bfloat16(v - __bfloat162float(h));
}

// 3-term MMA core (term-major), A/B rows stride 144B.
__device__ __forceinline__ void mma_block(float acc[2][8][4], unsigned AHI, unsigned ALO,
                                          unsigned BHI, unsigned BLO, int mB, int nB, int lane) {
    #pragma unroll
    for (int kt = 0; kt < 4; kt++) {
        const unsigned ka = (kt * 16 + ((lane >> 4) * 8)) * 2;
        const unsigned kb = (kt * 16 + (((lane >> 3) & 1) * 8)) * 2;
        unsigned ah[2][4], al[2][4];
        #pragma unroll
        for (int mi = 0; mi < 2; mi++) {
            unsigned ao = (mB + mi * 16 + (lane & 15)) * 144 + ka;
            ldsm4(ah[mi], AHI + ao);
            ldsm4(al[mi], ALO + ao);
        }
        unsigned bh[4][4], bl[4][4];
        #pragma unroll
        for (int np = 0; np < 4; np++) {
            unsigned bo = (nB + np * 16 + (lane & 7) + ((lane >> 4) * 8)) * 144 + kb;
            ldsm4(bh[np], BHI + bo);
            ldsm4(bl[np], BLO + bo);
        }
        #pragma unroll
        for (int mi = 0; mi < 2; mi++)
            #pragma unroll
            for (int np = 0; np < 4; np++) {
                mma16816(acc[mi][np * 2],     ah[mi], &bh[np][0]);
                mma16816(acc[mi][np * 2 + 1], ah[mi], &bh[np][2]);
            }
        #pragma unroll
        for (int mi = 0; mi < 2; mi++)
            #pragma unroll
            for (int np = 0; np < 4; np++) {
                mma16816(acc[mi][np * 2],     ah[mi], &bl[np][0]);
                mma16816(acc[mi][np * 2 + 1], ah[mi], &bl[np][2]);
            }
        #pragma unroll
        for (int mi = 0; mi < 2; mi++)
            #pragma unroll
            for (int np = 0; np < 4; np++) {
                mma16816(acc[mi][np * 2],     al[mi], &bh[np][0]);
                mma16816(acc[mi][np * 2 + 1], al[mi], &bh[np][2]);
            }
    }
}

// K0: bit-pack adjacency
__global__ void bitpack_kernel(const int* __restrict__ adj) {
    int idx = blockIdx.x * 256 + threadIdx.x;
    int4 v = ((const int4*)adj)[idx];
    unsigned b = (v.x > 0 ? 1u : 0u) | (v.y > 0 ? 2u : 0u)
               | (v.z > 0 ? 4u : 0u) | (v.w > 0 ? 8u : 0u);
    b |= __shfl_xor_sync(~0u, b, 1) << 4;
    b |= __shfl_xor_sync(~0u, b, 2) << 8;
    b |= __shfl_xor_sync(~0u, b, 4) << 16;
    if ((threadIdx.x & 7) == 0) g_adjbits[idx >> 3] = b;
}

// K0b: x -> bf16 hi/lo
__global__ void xcvt_kernel(const float* __restrict__ x) {
    int i = blockIdx.x * 256 + threadIdx.x;
    float4 v = ((const float4*)x)[i];
    __nv_bfloat16 h[4], l[4];
    bfsplit(v.x, h[0], l[0]); bfsplit(v.y, h[1], l[1]);
    bfsplit(v.z, h[2], l[2]); bfsplit(v.w, h[3], l[3]);
    *(ull*)&g_xhi[i * 4] = *(ull*)h;
    *(ull*)&g_xlo[i * 4] = *(ull*)l;
}

// K0c: W -> WT bf16 hi/lo
__global__ void wcvt_kernel(const float* __restrict__ W) {
    int idx = blockIdx.x * 256 + threadIdx.x;
    int h = idx >> 17, rem = idx & 131071;
    int d = rem >> 10, k = rem & 1023;
    float v = W[h * (NFEAT * NHID) + k * NHID + d];
    __nv_bfloat16 hb, lb; bfsplit(v, hb, lb);
    g_WThi[idx] = hb; g_WTlo[idx] = lb;
}

// K1: Wh = x @ W via mma.sync bf16 3-term — SINGLE STAGE, 2 CTAs/SM
#define WH_ST 73728
__global__ __launch_bounds__(256, 2) void wh_mma() {
    extern __shared__ __align__(16) char smx[];
    const unsigned sb = (unsigned)__cvta_generic_to_shared(smx);
    const int tid = threadIdx.x, lane = tid & 31, w = tid >> 5;
    const int m0 = blockIdx.x * 128, h = blockIdx.y;
    const int mB = (w & 3) * 32, nB = (w >> 2) * 64;

    float acc[2][8][4];
    #pragma unroll
    for (int mi = 0; mi < 2; mi++)
        #pragma unroll
        for (int nt = 0; nt < 8; nt++)
            #pragma unroll
            for (int e = 0; e < 4; e++) acc[mi][nt][e] = 0.f;

    const __nv_bfloat16* WTh = g_WThi + (size_t)h * NHID * NFEAT;
    const __nv_bfloat16* WTl = g_WTlo + (size_t)h * NHID * NFEAT;

    for (int t = 0; t < 16; t++) {
        size_t ko = (size_t)t * 64;
        #pragma unroll
        for (int q = 0; q < 4; q++) {
            int idx = tid + q * 256; int row = idx >> 3, ch = idx & 7;
            unsigned off = row * 144 + ch * 16;
            cp16(smx + off,         g_xhi + (size_t)(m0 + row) * NFEAT + ko + ch * 8);
            cp16(smx + 18432 + off, g_xlo + (size_t)(m0 + row) * NFEAT + ko + ch * 8);
            cp16(smx + 36864 + off, WTh + (size_t)row * NFEAT + ko + ch * 8);
            cp16(smx + 55296 + off, WTl + (size_t)row * NFEAT + ko + ch * 8);
        }
        CP_COMMIT(); CP_WAIT0();
        __syncthreads();
        mma_block(acc, sb, sb + 18432, sb + 36864, sb + 55296, mB, nB, lane);
        __syncthreads();
    }
    #pragma unroll
    for (int mi = 0; mi < 2; mi++)
        #pragma unroll
        for (int eh = 0; eh < 2; eh++) {
            int row = mB + mi * 16 + (lane >> 2) + eh * 8;
            float* dst = g_Wh + ((size_t)h * N_NODES + m0 + row) * NHID + nB + (lane & 3) * 2;
            #pragma unroll
            for (int nt = 0; nt < 8; nt++)
                *(float2*)(dst + nt * 8) = make_float2(acc[mi][nt][eh * 2], acc[mi][nt][eh * 2 + 1]);
        }
}

// K1t: Wh -> WhT hi/lo (coalesced tile transpose)
__global__ __launch_bounds__(256) void whT_kernel() {
    __shared__ float tile[64][65];
    const int h = blockIdx.z, d0 = blockIdx.y * 64, n0 = blockIdx.x * 64;
    const int tid = threadIdx.x;
    #pragma unroll
    for (int q = 0; q < 16; q++) {
        int lin = tid + q * 256;
        int row = lin >> 6, col = lin & 63;
        tile[row][col] = g_Wh[((size_t)h * N_NODES + n0 + row) * NHID + d0 + col];
    }
    __syncthreads();
    #pragma unroll
    for (int q = 0; q < 8; q++) {
        int lin = tid + q * 256;
        int drow = lin >> 5, np = (lin & 31) * 2;
        float v0 = tile[np][drow], v1 = tile[np + 1][drow];
        __nv_bfloat16 h0, l0, h1, l1;
        bfsplit(v0, h0, l0); bfsplit(v1, h1, l1);
        unsigned hw = (unsigned)__bfloat16_as_ushort(h0) | ((unsigned)__bfloat16_as_ushort(h1) << 16);
        unsigned lw = (unsigned)__bfloat16_as_ushort(l0) | ((unsigned)__bfloat16_as_ushort(l1) << 16);
        size_t o = ((size_t)h * NHID + d0 + drow) * N_NODES + n0 + np;
        *(unsigned*)&g_WhT_hi[o] = hw;
        *(unsigned*)&g_WhT_lo[o] = lw;
    }
}

// K1b: f1/f2 + factored exps
__global__ void f12_kernel(const float* __restrict__ a1, const float* __restrict__ a2) {
    int gw = (blockIdx.x * blockDim.x + threadIdx.x) >> 5;
    int lane = threadIdx.x & 31;
    if (gw >= NHEADS * N_NODES) return;
    int h = gw >> 12;
    const float* wh = g_Wh + (size_t)gw * NHID;
    const float* A1 = a1 + h * NHID;
    const float* A2 = a2 + h * NHID;
    float s1 = 0.f, s2 = 0.f;
    #pragma unroll
    for (int d = lane; d < NHID; d += 32) {
        float v = wh[d];
        s1 += v * A1[d]; s2 += v * A2[d];
    }
    #pragma unroll
    for (int o = 16; o; o >>= 1) {
        s1 += __shfl_xor_sync(~0u, s1, o);
        s2 += __shfl_xor_sync(~0u, s2, o);
    }
    if (lane == 0) {
        g_f1[gw] = s1; g_f2[gw] = s2;
        g_e1[gw] = make_float2(__expf(s1), __expf(ALPHA_LRELU * s1));
        g_e2[gw] = make_float2(__expf(s2), __expf(ALPHA_LRELU * s2));
    }
}

// K2: attn layer-1 — SINGLE STAGE, 2 CTAs/SM
#define OFF_WS  0
#define OFF_P   36864
#define OFF_LP  73728
#define SMEM_ATTN1 74752

__global__ __launch_bounds__(256, 2) void gat_attn1() {
    extern __shared__ __align__(16) char smx[];
    const unsigned sb = (unsigned)__cvta_generic_to_shared(smx);
    const int tid = threadIdx.x, lane = tid & 31, w = tid >> 5;
    const int h = blockIdx.y, i0 = blockIdx.x * 128;
    const int hN = h * N_NODES;

    const int rg = w & 3, jh = w >> 2;
    const int r = rg * 32 + lane, arow = i0 + r;
    const float f1r = g_f1[hN + arow];
    const float2 e1 = g_e1[hN + arow];
    float lacc = 0.f;

    const int mB = (w & 3) * 32, nB = (w >> 2) * 64;
    float acc[2][8][4];
    #pragma unroll
    for (int mi = 0; mi < 2; mi++)
        #pragma unroll
        for (int nt = 0; nt < 8; nt++)
            #pragma unroll
            for (int e = 0; e < 4; e++) acc[mi][nt][e] = 0.f;

    const __nv_bfloat16* WTh = g_WhT_hi + (size_t)h * NHID * N_NODES;
    const __nv_bfloat16* WTl = g_WhT_lo + (size_t)h * NHID * N_NODES;

    for (int t = 0; t < 64; t++) {
        // load W tile (single buffer; prev trailing sync guarantees mma done)
        {
            size_t so = (size_t)t * 64;
            #pragma unroll
            for (int q = 0; q < 4; q++) {
                int idx = tid + q * 256; int d = idx >> 3, ch = idx & 7;
                cp16(smx + OFF_WS + d * 144 + ch * 16,         WTh + (size_t)d * N_NODES + so + ch * 8);
                cp16(smx + OFF_WS + 18432 + d * 144 + ch * 16, WTl + (size_t)d * N_NODES + so + ch * 8);
            }
            CP_COMMIT();
        }
        // P tile (exp-free product form)
        {
            char* pstg = smx + OFF_P;
            unsigned word = g_adjbits[(size_t)arow * NWORDS + t * 2 + jh];
            float f2v = g_f2[hN + t * 64 + jh * 32 + lane];
            float2 e2v = g_e2[hN + t * 64 + jh * 32 + lane];
            unsigned pbase = r * 144 + jh * 64;
            #pragma unroll
            for (int jq = 0; jq < 8; jq++) {
                unsigned hv[2], lv[2];
                #pragma unroll
                for (int u = 0; u < 2; u++) {
                    float p[2];
                    #pragma unroll
                    for (int vv = 0; vv < 2; vv++) {
                        int j = jq * 4 + u * 2 + vv;
                        float f2j = __shfl_sync(~0u, f2v, j);
                        float ep  = __shfl_sync(~0u, e2v.x, j);
                        float en  = __shfl_sync(~0u, e2v.y, j);
                        float pv = (f1r + f2j > 0.f) ? e1.x * ep : e1.y * en;
                        pv = ((word >> j) & 1u) ? pv : 0.f;
                        lacc += pv;
                        p[vv] = pv;
                    }
                    __nv_bfloat16 h0, l0, h1, l1;
                    bfsplit(p[0], h0, l0); bfsplit(p[1], h1, l1);
                    hv[u] = (unsigned)__bfloat16_as_ushort(h0) | ((unsigned)__bfloat16_as_ushort(h1) << 16);
                    lv[u] = (unsigned)__bfloat16_as_ushort(l0) | ((unsigned)__bfloat16_as_ushort(l1) << 16);
                }
                ull hp; asm("mov.b64 %0,{%1,%2};" : "=l"(hp) : "r"(hv[0]), "r"(hv[1]));
                ull lp; asm("mov.b64 %0,{%1,%2};" : "=l"(lp) : "r"(lv[0]), "r"(lv[1]));
                *(ull*)(pstg + pbase + jq * 8) = hp;
                *(ull*)(pstg + 18432 + pbase + jq * 8) = lp;
            }
        }
        CP_WAIT0();
        __syncthreads();
        mma_block(acc, sb + OFF_P, sb + OFF_P + 18432, sb + OFF_WS, sb + OFF_WS + 18432, mB, nB, lane);
        __syncthreads();
    }
    ((float*)(smx + OFF_LP))[jh * 128 + r] = lacc;
    __syncthreads();
    {
        const float* LP = (const float*)(smx + OFF_LP);
        #pragma unroll
        for (int mi = 0; mi < 2; mi++)
            #pragma unroll
            for (int eh = 0; eh < 2; eh++) {
                int row = mB + mi * 16 + (lane >> 2) + eh * 8;
                float inv = 1.f / (LP[row] + LP[128 + row]);
                float* dst = g_hcat + (size_t)(i0 + row) * (NHEADS * NHID) + h * NHID + nB + (lane & 3) * 2;
                #pragma unroll
                for (int nt = 0; nt < 8; nt++) {
                    float v0 = acc[mi][nt][eh * 2] * inv;
                    float v1 = acc[mi][nt][eh * 2 + 1] * inv;
                    v0 = (v0 > 0.f) ? v0 : expm1f(v0);
                    v1 = (v1 > 0.f) ? v1 : expm1f(v1);
                    *(float2*)(dst + nt * 8) = make_float2(v0, v1);
                }
            }
    }
}

// K3: Who = hcat @ Wo (split-K=4, f32x2)
__global__ __launch_bounds__(256) void who_gemm(const float* __restrict__ Wo) {
    __shared__ float As[16][128];
    __shared__ float Bs[16][64];
    const int m0 = blockIdx.x * 128, kb = blockIdx.y;
    const int tid = threadIdx.x;
    const int tr = tid >> 4, tc = tid & 15;
    const int am = tid >> 1, ak = (tid & 1) * 8;
    const int bk = tid >> 4, bn = (tid & 15) * 4;

    ull acc[8][2];
    #pragma unroll
    for (int i = 0; i < 8; i++) { acc[i][0] = 0ull; acc[i][1] = 0ull; }
    const int kbeg = kb * 256, kend = kbeg + 256;
    for (int k0 = kbeg; k0 < kend; k0 += 16) {
        float4 a0 = *(const float4*)(g_hcat + (size_t)(m0 + am) * (NHEADS * NHID) + k0 + ak);
        float4 a1v = *(const float4*)(g_hcat + (size_t)(m0 + am) * (NHEADS * NHID) + k0 + ak + 4);
        As[ak + 0][am] = a0.x; As[ak + 1][am] = a0.y;
        As[ak + 2][am] = a0.z; As[ak + 3][am] = a0.w;
        As[ak + 4][am] = a1v.x; As[ak + 5][am] = a1v.y;
        As[ak + 6][am] = a1v.z; As[ak + 7][am] = a1v.w;
        *(float4*)&Bs[bk][bn] = *(const float4*)(Wo + (size_t)(k0 + bk) * NCLASS + bn);
        __syncthreads();
        #pragma unroll
        for (int k = 0; k < 16; k++) {
            float a[8];
            *(float4*)&a[0] = *(float4*)&As[k][tr * 8];
            *(float4*)&a[4] = *(float4*)&As[k][tr * 8 + 4];
            ulonglong2 b = *(ulonglong2*)&Bs[k][tc * 4];
            #pragma unroll
            for (int i = 0; i < 8; i++) {
                ull ap = pack2(a[i], a[i]);
                acc[i][0] = fma2(ap, b.x, acc[i][0]);
                acc[i][1] = fma2(ap, b.y, acc[i][1]);
            }
        }
        __syncthreads();
    }
    float* C = g_WhoP + (size_t)kb * N_NODES * NCLASS;
    #pragma unroll
    for (int i = 0; i < 8; i++) {
        ulonglong2 v; v.x = acc[i][0]; v.y = acc[i][1];
        *(ulonglong2*)(C + (size_t)(m0 + tr * 8 + i) * NCLASS + tc * 4) = v;
    }
}

// K3b: reduce split-K, g1/g2 exps
__global__ void g12_kernel(const float* __restrict__ ao1, const float* __restrict__ ao2) {
    int gw = (blockIdx.x * blockDim.x + threadIdx.x) >> 5;
    int lane = threadIdx.x & 31;
    if (gw >= N_NODES) return;
    size_t base = (size_t)gw * NCLASS;
    float v1 = 0.f, v2 = 0.f;
    #pragma unroll
    for (int kb = 0; kb < 4; kb++) {
        v1 += g_WhoP[(size_t)kb * N_NODES * NCLASS + base + lane];
        v2 += g_WhoP[(size_t)kb * N_NODES * NCLASS + base + lane + 32];
    }
    g_Who[base + lane] = v1;
    g_Who[base + lane + 32] = v2;
    float s1 = v1 * ao1[lane] + v2 * ao1[lane + 32];
    float s2 = v1 * ao2[lane] + v2 * ao2[lane + 32];
    #pragma unroll
    for (int o = 16; o; o >>= 1) {
        s1 += __shfl_xor_sync(~0u, s1, o);
        s2 += __shfl_xor_sync(~0u, s2, o);
    }
    if (lane == 0) {
        g_g1[gw] = s1;
        g_eo1[gw] = make_float2(__expf(s1), __expf(ALPHA_LRELU * s1));
        g_eo2[gw] = make_float2(__expf(s2), __expf(ALPHA_LRELU * s2));
    }
}

// K4: output attention — pipelined scalar
__global__ __launch_bounds__(256) void gat_attn2(float* __restrict__ out) {
    __shared__ float VS[2][64][NCLASS];
    __shared__ float P[2][32][65];
    __shared__ float l_s[32];
    const int i0 = blockIdx.x * 32;
    const int tid = threadIdx.x, lane = tid & 31, w = tid >> 5;

    float2 e1v[4]; float lacc[4];
    #pragma unroll
    for (int rr = 0; rr < 4; rr++) {
        e1v[rr] = g_eo1[i0 + w * 4 + rr];
        lacc[rr] = 0.f;
    }
    const int tr = tid >> 4, tc = tid & 15;
    ull O[2][2];
    O[0][0] = 0ull; O[0][1] = 0ull; O[1][0] = 0ull; O[1][1] = 0ull;

    #define VS_LD(tt, ss) { _Pragma("unroll") for (int q = 0; q < 4; q++) { \
        int idx = tid + q * 256; int row = idx >> 4, c = (idx & 15) * 4; \
        *(float4*)&VS[ss][row][c] = *(const float4*)(g_Who + (size_t)((tt) * 64 + row) * NCLASS + c); } }

    #define P_GEN2(tt, ss) { \
        float2 eo2a = g_eo2[(tt) * 64 + lane]; \
        float2 eo2b = g_eo2[(tt) * 64 + 32 + lane]; \
        _Pragma("unroll") for (int rr = 0; rr < 4; rr++) { \
            int rq = w * 4 + rr; \
            uint2 bw = *(const uint2*)&g_adjbits[(size_t)(i0 + rq) * NWORDS + (tt) * 2]; \
            float pr1 = e1v[rr].x * eo2a.x; \
            float pr2 = e1v[rr].x * eo2b.x; \
            float p1 = (pr1 > 1.f) ? pr1 : e1v[rr].y * eo2a.y; \
            float p2 = (pr2 > 1.f) ? pr2 : e1v[rr].y * eo2b.y; \
            p1 = ((bw.x >> lane) & 1u) ? p1 : 0.f; \
            p2 = ((bw.y >> lane) & 1u) ? p2 : 0.f; \
            P[ss][rq][lane] = p1; P[ss][rq][lane + 32] = p2; \
            lacc[rr] += p1 + p2; } }

    VS_LD(0, 0); P_GEN2(0, 0);
    __syncthreads();
    for (int t = 0; t < 64; t++) {
        const int s = t & 1;
        #pragma unroll 4
        for (int j = 0; j < 64; j++) {
            ulonglong2 wv = *(ulonglong2*)&VS[s][j][tc * 4];
            float pa = P[s][tr * 2][j], pb = P[s][tr * 2 + 1][j];
            ull ppa = pack2(pa, pa), ppb = pack2(pb, pb);
            O[0][0] = fma2(ppa, wv.x, O[0][0]);
            O[0][1] = fma2(ppa, wv.y, O[0][1]);
            O[1][0] = fma2(ppb, wv.x, O[1][0]);
            O[1][1] = fma2(ppb, wv.y, O[1][1]);
        }
        if (t + 1 < 64) { VS_LD(t + 1, (t + 1) & 1); P_GEN2(t + 1, (t + 1) & 1); }
        __syncthreads();
    }
    #pragma unroll
    for (int rr = 0; rr < 4; rr++) {
        float v = lacc[rr];
        #pragma unroll
        for (int o = 16; o; o >>= 1) v += __shfl_xor_sync(~0u, v, o);
        if (lane == 0) l_s[w * 4 + rr] = v;
    }
    __syncthreads();
    #pragma unroll
    for (int a = 0; a < 2; a++) {
        int rq = tr * 2 + a;
        float inv = 1.f / l_s[rq];
        float o[4];
        float2 u0 = unpack2(O[a][0]); o[0] = u0.x * inv; o[1] = u0.y * inv;
        float2 u1 = unpack2(O[a][1]); o[2] = u1.x * inv; o[3] = u1.y * inv;
        #pragma unroll
        for (int b = 0; b < 4; b++) o[b] = (o[b] > 0.f) ? o[b] : expm1f(o[b]);
        *(float4*)(out + (size_t)(i0 + rq) * NCLASS + tc * 4) = *(float4*)&o[0];
    }
}

// K5: log_softmax
__global__ void logsoftmax_kernel(float* __restrict__ out) {
    int gw = (blockIdx.x * blockDim.x + threadIdx.x) >> 5;
    int lane = threadIdx.x & 31;
    if (gw >= N_NODES) return;
    float* row = out + (size_t)gw * NCLASS;
    float v1 = row[lane], v2 = row[lane + 32];
    float m = fmaxf(v1, v2);
    #pragma unroll
    for (int o = 16; o; o >>= 1) m = fmaxf(m, __shfl_xor_sync(~0u, m, o));
    float s = __expf(v1 - m) + __expf(v2 - m);
    #pragma unroll
    for (int o = 16; o; o >>= 1) s += __shfl_xor_sync(~0u, s, o);
    float ls = m + logf(s);
    row[lane] = v1 - ls;
    row[lane + 32] = v2 - ls;
}

extern "C" void kernel_launch(void* const* d_in, const int* in_sizes, int n_in,
                              void* d_out, int out_size) {
    const float* x   = (const float*)d_in[0];
    const int*   adj = (const int*)  d_in[1];
    const float* W   = (const float*)d_in[2];
    const float* a1  = (const float*)d_in[3];
    const float* a2  = (const float*)d_in[4];
    const float* Wo  = (const float*)d_in[5];
    const float* ao1 = (const float*)d_in[6];
    const float* ao2 = (const float*)d_in[7];
    float* out = (float*)d_out;

    cudaFuncSetAttribute(gat_attn1, cudaFuncAttributeMaxDynamicSharedMemorySize, SMEM_ATTN1);
    cudaFuncSetAttribute(wh_mma, cudaFuncAttributeMaxDynamicSharedMemorySize, WH_ST);

    bitpack_kernel<<<(N_NODES * N_NODES / 4) / 256, 256>>>(adj);
    xcvt_kernel<<<(N_NODES * NFEAT / 4) / 256, 256>>>(x);
    wcvt_kernel<<<(NHEADS * NHID * NFEAT) / 256, 256>>>(W);
    wh_mma<<<dim3(N_NODES / 128, NHEADS), 256, WH_ST>>>();
    whT_kernel<<<dim3(N_NODES / 64, NHID / 64, NHEADS), 256>>>();
    f12_kernel<<<(NHEADS * N_NODES) / 8, 256>>>(a1, a2);
    gat_attn1<<<dim3(N_NODES / 128, NHEADS), 256, SMEM_ATTN1>>>();
    who_gemm<<<dim3(N_NODES / 128, 4), 256>>>(Wo);
    g12_kernel<<<N_NODES / 8, 256>>>(ao1, ao2);
    gat_attn2<<<N_NODES / 32, 256>>>(out);
    logsoftmax_kernel<<<N_NODES / 8, 256>>>(out);
}

// round 16
// speedup vs baseline: 1.2406x; 1.1207x over previous
#include <cuda_runtime.h>
#include <cuda_bf16.h>
#include <math.h>

#define N_NODES 4096
#define NFEAT   1024
#define NHID    128
#define NHEADS  8
#define NCLASS  64
#define NWORDS  (N_NODES / 32)
#define ALPHA_LRELU 0.2f

__device__ float g_Wh[NHEADS * N_NODES * NHID];
__device__ __nv_bfloat16 g_xhi[N_NODES * NFEAT];
__device__ __nv_bfloat16 g_xlo[N_NODES * NFEAT];
__device__ __nv_bfloat16 g_WThi[NHEADS * NHID * NFEAT];
__device__ __nv_bfloat16 g_WTlo[NHEADS * NHID * NFEAT];
__device__ __nv_bfloat16 g_WhT_hi[NHEADS * NHID * N_NODES];
__device__ __nv_bfloat16 g_WhT_lo[NHEADS * NHID * N_NODES];
__device__ float g_f1[NHEADS * N_NODES];
__device__ float g_f2[NHEADS * N_NODES];
__device__ float2 g_e1[NHEADS * N_NODES];
__device__ float2 g_e2[NHEADS * N_NODES];
__device__ float g_hcat[N_NODES * NHEADS * NHID];
__device__ float g_WhoP[4 * N_NODES * NCLASS];
__device__ float g_Who[N_NODES * NCLASS];
__device__ __nv_bfloat16 g_WhoT_hi[NCLASS * N_NODES];
__device__ __nv_bfloat16 g_WhoT_lo[NCLASS * N_NODES];
__device__ float2 g_eo1[N_NODES];
__device__ float2 g_eo2[N_NODES];
__device__ unsigned g_adjbits[N_NODES * NWORDS];

typedef unsigned long long ull;

__device__ __forceinline__ ull pack2(float lo, float hi) {
    ull r; asm("mov.b64 %0,{%1,%2};" : "=l"(r) : "f"(lo), "f"(hi)); return r;
}
__device__ __forceinline__ ull fma2(ull a, ull b, ull c) {
    ull d; asm("fma.rn.f32x2 %0,%1,%2,%3;" : "=l"(d) : "l"(a), "l"(b), "l"(c)); return d;
}
__device__ __forceinline__ void cp16(void* dst, const void* src) {
    unsigned sa = (unsigned)__cvta_generic_to_shared(dst);
    asm volatile("cp.async.cg.shared.global [%0], [%1], 16;" :: "r"(sa), "l"(src));
}
#define CP_COMMIT() asm volatile("cp.async.commit_group;")
#define CP_WAIT0()  asm volatile("cp.async.wait_group 0;")

__device__ __forceinline__ void ldsm4(unsigned* r, unsigned a) {
    asm volatile("ldmatrix.sync.aligned.m8n8.x4.shared.b16 {%0,%1,%2,%3}, [%4];"
                 : "=r"(r[0]), "=r"(r[1]), "=r"(r[2]), "=r"(r[3]) : "r"(a));
}
__device__ __forceinline__ void mma16816(float* d, const unsigned* a, const unsigned* b) {
    asm volatile("mma.sync.aligned.m16n8k16.row.col.f32.bf16.bf16.f32 "
                 "{%0,%1,%2,%3}, {%4,%5,%6,%7}, {%8,%9}, {%0,%1,%2,%3};"
                 : "+f"(d[0]), "+f"(d[1]), "+f"(d[2]), "+f"(d[3])
                 : "r"(a[0]), "r"(a[1]), "r"(a[2]), "r"(a[3]), "r"(b[0]), "r"(b[1]));
}
__device__ __forceinline__ void bfsplit(float v, __nv_bfloat16& h, __nv_bfloat16& l) {
    h = __float2bfloat16(v);
    l = __float2bfloat16(v - __bfloat162float(h));
}

// 3-term MMA core (term-major), A/B rows stride 144B.
__device__ __forceinline__ void mma_block(float acc[2][8][4], unsigned AHI, unsigned ALO,
                                          unsigned BHI, unsigned BLO, int mB, int nB, int lane) {
    #pragma unroll
    for (int kt = 0; kt < 4; kt++) {
        const unsigned ka = (kt * 16 + ((lane >> 4) * 8)) * 2;
        const unsigned kb = (kt * 16 + (((lane >> 3) & 1) * 8)) * 2;
        unsigned ah[2][4], al[2][4];
        #pragma unroll
        for (int mi = 0; mi < 2; mi++) {
            unsigned ao = (mB + mi * 16 + (lane & 15)) * 144 + ka;
            ldsm4(ah[mi], AHI + ao);
            ldsm4(al[mi], ALO + ao);
        }
        unsigned bh[4][4], bl[4][4];
        #pragma unroll
        for (int np = 0; np < 4; np++) {
            unsigned bo = (nB + np * 16 + (lane & 7) + ((lane >> 4) * 8)) * 144 + kb;
            ldsm4(bh[np], BHI + bo);
            ldsm4(bl[np], BLO + bo);
        }
        #pragma unroll
        for (int mi = 0; mi < 2; mi++)
            #pragma unroll
            for (int np = 0; np < 4; np++) {
                mma16816(acc[mi][np * 2],     ah[mi], &bh[np][0]);
                mma16816(acc[mi][np * 2 + 1], ah[mi], &bh[np][2]);
            }
        #pragma unroll
        for (int mi = 0; mi < 2; mi++)
            #pragma unroll
            for (int np = 0; np < 4; np++) {
                mma16816(acc[mi][np * 2],     ah[mi], &bl[np][0]);
                mma16816(acc[mi][np * 2 + 1], ah[mi], &bl[np][2]);
            }
        #pragma unroll
        for (int mi = 0; mi < 2; mi++)
            #pragma unroll
            for (int np = 0; np < 4; np++) {
                mma16816(acc[mi][np * 2],     al[mi], &bh[np][0]);
                mma16816(acc[mi][np * 2 + 1], al[mi], &bh[np][2]);
            }
    }
}

// K0: bit-pack adjacency
__global__ void bitpack_kernel(const int* __restrict__ adj) {
    int idx = blockIdx.x * 256 + threadIdx.x;
    int4 v = ((const int4*)adj)[idx];
    unsigned b = (v.x > 0 ? 1u : 0u) | (v.y > 0 ? 2u : 0u)
               | (v.z > 0 ? 4u : 0u) | (v.w > 0 ? 8u : 0u);
    b |= __shfl_xor_sync(~0u, b, 1) << 4;
    b |= __shfl_xor_sync(~0u, b, 2) << 8;
    b |= __shfl_xor_sync(~0u, b, 4) << 16;
    if ((threadIdx.x & 7) == 0) g_adjbits[idx >> 3] = b;
}

// K0b: x -> bf16 hi/lo
__global__ void xcvt_kernel(const float* __restrict__ x) {
    int i = blockIdx.x * 256 + threadIdx.x;
    float4 v = ((const float4*)x)[i];
    __nv_bfloat16 h[4], l[4];
    bfsplit(v.x, h[0], l[0]); bfsplit(v.y, h[1], l[1]);
    bfsplit(v.z, h[2], l[2]); bfsplit(v.w, h[3], l[3]);
    *(ull*)&g_xhi[i * 4] = *(ull*)h;
    *(ull*)&g_xlo[i * 4] = *(ull*)l;
}

// K0c: W -> WT bf16 hi/lo
__global__ void wcvt_kernel(const float* __restrict__ W) {
    int idx = blockIdx.x * 256 + threadIdx.x;
    int h = idx >> 17, rem = idx & 131071;
    int d = rem >> 10, k = rem & 1023;
    float v = W[h * (NFEAT * NHID) + k * NHID + d];
    __nv_bfloat16 hb, lb; bfsplit(v, hb, lb);
    g_WThi[idx] = hb; g_WTlo[idx] = lb;
}

// K1: Wh = x @ W via mma.sync bf16 3-term — single stage, 2 CTAs/SM
#define WH_ST 73728
__global__ __launch_bounds__(256, 2) void wh_mma() {
    extern __shared__ __align__(16) char smx[];
    const unsigned sb = (unsigned)__cvta_generic_to_shared(smx);
    const int tid = threadIdx.x, lane = tid & 31, w = tid >> 5;
    const int m0 = blockIdx.x * 128, h = blockIdx.y;
    const int mB = (w & 3) * 32, nB = (w >> 2) * 64;

    float acc[2][8][4];
    #pragma unroll
    for (int mi = 0; mi < 2; mi++)
        #pragma unroll
        for (int nt = 0; nt < 8; nt++)
            #pragma unroll
            for (int e = 0; e < 4; e++) acc[mi][nt][e] = 0.f;

    const __nv_bfloat16* WTh = g_WThi + (size_t)h * NHID * NFEAT;
    const __nv_bfloat16* WTl = g_WTlo + (size_t)h * NHID * NFEAT;

    for (int t = 0; t < 16; t++) {
        size_t ko = (size_t)t * 64;
        #pragma unroll
        for (int q = 0; q < 4; q++) {
            int idx = tid + q * 256; int row = idx >> 3, ch = idx & 7;
            unsigned off = row * 144 + ch * 16;
            cp16(smx + off,         g_xhi + (size_t)(m0 + row) * NFEAT + ko + ch * 8);
            cp16(smx + 18432 + off, g_xlo + (size_t)(m0 + row) * NFEAT + ko + ch * 8);
            cp16(smx + 36864 + off, WTh + (size_t)row * NFEAT + ko + ch * 8);
            cp16(smx + 55296 + off, WTl + (size_t)row * NFEAT + ko + ch * 8);
        }
        CP_COMMIT(); CP_WAIT0();
        __syncthreads();
        mma_block(acc, sb, sb + 18432, sb + 36864, sb + 55296, mB, nB, lane);
        __syncthreads();
    }
    #pragma unroll
    for (int mi = 0; mi < 2; mi++)
        #pragma unroll
        for (int eh = 0; eh < 2; eh++) {
            int row = mB + mi * 16 + (lane >> 2) + eh * 8;
            float* dst = g_Wh + ((size_t)h * N_NODES + m0 + row) * NHID + nB + (lane & 3) * 2;
            #pragma unroll
            for (int nt = 0; nt < 8; nt++)
                *(float2*)(dst + nt * 8) = make_float2(acc[mi][nt][eh * 2], acc[mi][nt][eh * 2 + 1]);
        }
}

// K1t: Wh -> WhT hi/lo (coalesced tile transpose)
__global__ __launch_bounds__(256) void whT_kernel() {
    __shared__ float tile[64][65];
    const int h = blockIdx.z, d0 = blockIdx.y * 64, n0 = blockIdx.x * 64;
    const int tid = threadIdx.x;
    #pragma unroll
    for (int q = 0; q < 16; q++) {
        int lin = tid + q * 256;
        int row = lin >> 6, col = lin & 63;
        tile[row][col] = g_Wh[((size_t)h * N_NODES + n0 + row) * NHID + d0 + col];
    }
    __syncthreads();
    #pragma unroll
    for (int q = 0; q < 8; q++) {
        int lin = tid + q * 256;
        int drow = lin >> 5, np = (lin & 31) * 2;
        float v0 = tile[np][drow], v1 = tile[np + 1][drow];
        __nv_bfloat16 h0, l0, h1, l1;
        bfsplit(v0, h0, l0); bfsplit(v1, h1, l1);
        unsigned hw = (unsigned)__bfloat16_as_ushort(h0) | ((unsigned)__bfloat16_as_ushort(h1) << 16);
        unsigned lw = (unsigned)__bfloat16_as_ushort(l0) | ((unsigned)__bfloat16_as_ushort(l1) << 16);
        size_t o = ((size_t)h * NHID + d0 + drow) * N_NODES + n0 + np;
        *(unsigned*)&g_WhT_hi[o] = hw;
        *(unsigned*)&g_WhT_lo[o] = lw;
    }
}

// K1b: f1/f2 + factored exps
__global__ void f12_kernel(const float* __restrict__ a1, const float* __restrict__ a2) {
    int gw = (blockIdx.x * blockDim.x + threadIdx.x) >> 5;
    int lane = threadIdx.x & 31;
    if (gw >= NHEADS * N_NODES) return;
    int h = gw >> 12;
    const float* wh = g_Wh + (size_t)gw * NHID;
    const float* A1 = a1 + h * NHID;
    const float* A2 = a2 + h * NHID;
    float s1 = 0.f, s2 = 0.f;
    #pragma unroll
    for (int d = lane; d < NHID; d += 32) {
        float v = wh[d];
        s1 += v * A1[d]; s2 += v * A2[d];
    }
    #pragma unroll
    for (int o = 16; o; o >>= 1) {
        s1 += __shfl_xor_sync(~0u, s1, o);
        s2 += __shfl_xor_sync(~0u, s2, o);
    }
    if (lane == 0) {
        g_f1[gw] = s1; g_f2[gw] = s2;
        g_e1[gw] = make_float2(__expf(s1), __expf(ALPHA_LRELU * s1));
        g_e2[gw] = make_float2(__expf(s2), __expf(ALPHA_LRELU * s2));
    }
}

// K2: attn layer-1 — single stage, 2 CTAs/SM
#define OFF_WS  0
#define OFF_P   36864
#define OFF_LP  73728
#define SMEM_ATTN1 74752

__global__ __launch_bounds__(256, 2) void gat_attn1() {
    extern __shared__ __align__(16) char smx[];
    const unsigned sb = (unsigned)__cvta_generic_to_shared(smx);
    const int tid = threadIdx.x, lane = tid & 31, w = tid >> 5;
    const int h = blockIdx.y, i0 = blockIdx.x * 128;
    const int hN = h * N_NODES;

    const int rg = w & 3, jh = w >> 2;
    const int r = rg * 32 + lane, arow = i0 + r;
    const float f1r = g_f1[hN + arow];
    const float2 e1 = g_e1[hN + arow];
    float lacc = 0.f;

    const int mB = (w & 3) * 32, nB = (w >> 2) * 64;
    float acc[2][8][4];
    #pragma unroll
    for (int mi = 0; mi < 2; mi++)
        #pragma unroll
        for (int nt = 0; nt < 8; nt++)
            #pragma unroll
            for (int e = 0; e < 4; e++) acc[mi][nt][e] = 0.f;

    const __nv_bfloat16* WTh = g_WhT_hi + (size_t)h * NHID * N_NODES;
    const __nv_bfloat16* WTl = g_WhT_lo + (size_t)h * NHID * N_NODES;

    for (int t = 0; t < 64; t++) {
        {
            size_t so = (size_t)t * 64;
            #pragma unroll
            for (int q = 0; q < 4; q++) {
                int idx = tid + q * 256; int d = idx >> 3, ch = idx & 7;
                cp16(smx + OFF_WS + d * 144 + ch * 16,         WTh + (size_t)d * N_NODES + so + ch * 8);
                cp16(smx + OFF_WS + 18432 + d * 144 + ch * 16, WTl + (size_t)d * N_NODES + so + ch * 8);
            }
            CP_COMMIT();
        }
        {
            char* pstg = smx + OFF_P;
            unsigned word = g_adjbits[(size_t)arow * NWORDS + t * 2 + jh];
            float f2v = g_f2[hN + t * 64 + jh * 32 + lane];
            float2 e2v = g_e2[hN + t * 64 + jh * 32 + lane];
            unsigned pbase = r * 144 + jh * 64;
            #pragma unroll
            for (int jq = 0; jq < 8; jq++) {
                unsigned hv[2], lv[2];
                #pragma unroll
                for (int u = 0; u < 2; u++) {
                    float p[2];
                    #pragma unroll
                    for (int vv = 0; vv < 2; vv++) {
                        int j = jq * 4 + u * 2 + vv;
                        float f2j = __shfl_sync(~0u, f2v, j);
                        float ep  = __shfl_sync(~0u, e2v.x, j);
                        float en  = __shfl_sync(~0u, e2v.y, j);
                        float pv = (f1r + f2j > 0.f) ? e1.x * ep : e1.y * en;
                        pv = ((word >> j) & 1u) ? pv : 0.f;
                        lacc += pv;
                        p[vv] = pv;
                    }
                    __nv_bfloat16 h0, l0, h1, l1;
                    bfsplit(p[0], h0, l0); bfsplit(p[1], h1, l1);
                    hv[u] = (unsigned)__bfloat16_as_ushort(h0) | ((unsigned)__bfloat16_as_ushort(h1) << 16);
                    lv[u] = (unsigned)__bfloat16_as_ushort(l0) | ((unsigned)__bfloat16_as_ushort(l1) << 16);
                }
                ull hp; asm("mov.b64 %0,{%1,%2};" : "=l"(hp) : "r"(hv[0]), "r"(hv[1]));
                ull lp; asm("mov.b64 %0,{%1,%2};" : "=l"(lp) : "r"(lv[0]), "r"(lv[1]));
                *(ull*)(pstg + pbase + jq * 8) = hp;
                *(ull*)(pstg + 18432 + pbase + jq * 8) = lp;
            }
        }
        CP_WAIT0();
        __syncthreads();
        mma_block(acc, sb + OFF_P, sb + OFF_P + 18432, sb + OFF_WS, sb + OFF_WS + 18432, mB, nB, lane);
        __syncthreads();
    }
    ((float*)(smx + OFF_LP))[jh * 128 + r] = lacc;
    __syncthreads();
    {
        const float* LP = (const float*)(smx + OFF_LP);
        #pragma unroll
        for (int mi = 0; mi < 2; mi++)
            #pragma unroll
            for (int eh = 0; eh < 2; eh++) {
                int row = mB + mi * 16 + (lane >> 2) + eh * 8;
                float inv = 1.f / (LP[row] + LP[128 + row]);
                float* dst = g_hcat + (size_t)(i0 + row) * (NHEADS * NHID) + h * NHID + nB + (lane & 3) * 2;
                #pragma unroll
                for (int nt = 0; nt < 8; nt++) {
                    float v0 = acc[mi][nt][eh * 2] * inv;
                    float v1 = acc[mi][nt][eh * 2 + 1] * inv;
                    v0 = (v0 > 0.f) ? v0 : expm1f(v0);
                    v1 = (v1 > 0.f) ? v1 : expm1f(v1);
                    *(float2*)(dst + nt * 8) = make_float2(v0, v1);
                }
            }
    }
}

// K3: Who = hcat @ Wo (split-K=4, f32x2)
__global__ __launch_bounds__(256) void who_gemm(const float* __restrict__ Wo) {
    __shared__ float As[16][128];
    __shared__ float Bs[16][64];
    const int m0 = blockIdx.x * 128, kb = blockIdx.y;
    const int tid = threadIdx.x;
    const int tr = tid >> 4, tc = tid & 15;
    const int am = tid >> 1, ak = (tid & 1) * 8;
    const int bk = tid >> 4, bn = (tid & 15) * 4;

    ull acc[8][2];
    #pragma unroll
    for (int i = 0; i < 8; i++) { acc[i][0] = 0ull; acc[i][1] = 0ull; }
    const int kbeg = kb * 256, kend = kbeg + 256;
    for (int k0 = kbeg; k0 < kend; k0 += 16) {
        float4 a0 = *(const float4*)(g_hcat + (size_t)(m0 + am) * (NHEADS * NHID) + k0 + ak);
        float4 a1v = *(const float4*)(g_hcat + (size_t)(m0 + am) * (NHEADS * NHID) + k0 + ak + 4);
        As[ak + 0][am] = a0.x; As[ak + 1][am] = a0.y;
        As[ak + 2][am] = a0.z; As[ak + 3][am] = a0.w;
        As[ak + 4][am] = a1v.x; As[ak + 5][am] = a1v.y;
        As[ak + 6][am] = a1v.z; As[ak + 7][am] = a1v.w;
        *(float4*)&Bs[bk][bn] = *(const float4*)(Wo + (size_t)(k0 + bk) * NCLASS + bn);
        __syncthreads();
        #pragma unroll
        for (int k = 0; k < 16; k++) {
            float a[8];
            *(float4*)&a[0] = *(float4*)&As[k][tr * 8];
            *(float4*)&a[4] = *(float4*)&As[k][tr * 8 + 4];
            ulonglong2 b = *(ulonglong2*)&Bs[k][tc * 4];
            #pragma unroll
            for (int i = 0; i < 8; i++) {
                ull ap = pack2(a[i], a[i]);
                acc[i][0] = fma2(ap, b.x, acc[i][0]);
                acc[i][1] = fma2(ap, b.y, acc[i][1]);
            }
        }
        __syncthreads();
    }
    float* C = g_WhoP + (size_t)kb * N_NODES * NCLASS;
    #pragma unroll
    for (int i = 0; i < 8; i++) {
        ulonglong2 v; v.x = acc[i][0]; v.y = acc[i][1];
        *(ulonglong2*)(C + (size_t)(m0 + tr * 8 + i) * NCLASS + tc * 4) = v;
    }
}

// K3b: reduce split-K, g1/g2 exps
__global__ void g12_kernel(const float* __restrict__ ao1, const float* __restrict__ ao2) {
    int gw = (blockIdx.x * blockDim.x + threadIdx.x) >> 5;
    int lane = threadIdx.x & 31;
    if (gw >= N_NODES) return;
    size_t base = (size_t)gw * NCLASS;
    float v1 = 0.f, v2 = 0.f;
    #pragma unroll
    for (int kb = 0; kb < 4; kb++) {
        v1 += g_WhoP[(size_t)kb * N_NODES * NCLASS + base + lane];
        v2 += g_WhoP[(size_t)kb * N_NODES * NCLASS + base + lane + 32];
    }
    g_Who[base + lane] = v1;
    g_Who[base + lane + 32] = v2;
    float s1 = v1 * ao1[lane] + v2 * ao1[lane + 32];
    float s2 = v1 * ao2[lane] + v2 * ao2[lane + 32];
    #pragma unroll
    for (int o = 16; o; o >>= 1) {
        s1 += __shfl_xor_sync(~0u, s1, o);
        s2 += __shfl_xor_sync(~0u, s2, o);
    }
    if (lane == 0) {
        g_eo1[gw] = make_float2(__expf(s1), __expf(ALPHA_LRELU * s1));
        g_eo2[gw] = make_float2(__expf(s2), __expf(ALPHA_LRELU * s2));
    }
}

// K3c: Who -> WhoT bf16 hi/lo (tile transpose), grid 64
__global__ __launch_bounds__(256) void whoT_kernel() {
    __shared__ float tile[64][65];
    const int n0 = blockIdx.x * 64;
    const int tid = threadIdx.x;
    #pragma unroll
    for (int q = 0; q < 16; q++) {
        int lin = tid + q * 256;
        int row = lin >> 6, col = lin & 63;
        tile[row][col] = g_Who[(size_t)(n0 + row) * NCLASS + col];
    }
    __syncthreads();
    #pragma unroll
    for (int q = 0; q < 8; q++) {
        int lin = tid + q * 256;
        int crow = lin >> 5, np = (lin & 31) * 2;
        float v0 = tile[np][crow], v1 = tile[np + 1][crow];
        __nv_bfloat16 h0, l0, h1, l1;
        bfsplit(v0, h0, l0); bfsplit(v1, h1, l1);
        unsigned hw = (unsigned)__bfloat16_as_ushort(h0) | ((unsigned)__bfloat16_as_ushort(h1) << 16);
        unsigned lw = (unsigned)__bfloat16_as_ushort(l0) | ((unsigned)__bfloat16_as_ushort(l1) << 16);
        size_t o = (size_t)crow * N_NODES + n0 + np;
        *(unsigned*)&g_WhoT_hi[o] = hw;
        *(unsigned*)&g_WhoT_lo[o] = lw;
    }
}

// K4: output attention on mma.sync bf16 3-term. grid 128 (32 rows/block).
#define A2_V   0
#define A2_P   18432
#define A2_LP  27648
#define SMEM_ATTN2 28672

__global__ __launch_bounds__(256) void gat_attn2_mma(float* __restrict__ out) {
    __shared__ __align__(16) char smx[SMEM_ATTN2];
    const unsigned sb = (unsigned)__cvta_generic_to_shared(smx);
    const int tid = threadIdx.x, lane = tid & 31, w = tid >> 5;
    const int i0 = blockIdx.x * 32;

    // producer role: row = lane, j-slice = w*8 .. w*8+7 within each 64-tile
    const float2 e1v = g_eo1[i0 + lane];
    float lacc = 0.f;

    // mma role: mB in {0,16}, nB in {0,16,32,48}
    const int mB = (w & 1) * 16, nB = (w >> 1) * 16;
    float acc[2][4];
    #pragma unroll
    for (int nt = 0; nt < 2; nt++)
        #pragma unroll
        for (int e = 0; e < 4; e++) acc[nt][e] = 0.f;

    for (int t = 0; t < 64; t++) {
        // load V tile: WhoT[c][t*64 + j], 64 rows x 128B
        #pragma unroll
        for (int q = 0; q < 2; q++) {
            int idx = tid + q * 256;
            int row = idx >> 3, ch = idx & 7;
            cp16(smx + A2_V + row * 144 + ch * 16,        g_WhoT_hi + (size_t)row * N_NODES + t * 64 + ch * 8);
            cp16(smx + A2_V + 9216 + row * 144 + ch * 16, g_WhoT_lo + (size_t)row * N_NODES + t * 64 + ch * 8);
        }
        CP_COMMIT();
        // P tile: rows = lanes, this warp's 8 j's
        {
            float2 e2v = g_eo2[t * 64 + w * 8 + (lane & 7)];
            unsigned word = g_adjbits[(size_t)(i0 + lane) * NWORDS + t * 2 + (w >> 2)];
            const int bo = (w & 3) * 8;
            unsigned pbase = A2_P + lane * 144 + w * 16;
            #pragma unroll
            for (int jp = 0; jp < 4; jp++) {
                float p[2];
                #pragma unroll
                for (int vv = 0; vv < 2; vv++) {
                    int jj = jp * 2 + vv;
                    float ex = __shfl_sync(~0u, e2v.x, jj);
                    float ey = __shfl_sync(~0u, e2v.y, jj);
                    float pr = e1v.x * ex;
                    float pv = (pr > 1.f) ? pr : e1v.y * ey;
                    pv = ((word >> (bo + jj)) & 1u) ? pv : 0.f;
                    lacc += pv;
                    p[vv] = pv;
                }
                __nv_bfloat16 h0, l0, h1, l1;
                bfsplit(p[0], h0, l0); bfsplit(p[1], h1, l1);
                unsigned hv = (unsigned)__bfloat16_as_ushort(h0) | ((unsigned)__bfloat16_as_ushort(h1) << 16);
                unsigned lv = (unsigned)__bfloat16_as_ushort(l0) | ((unsigned)__bfloat16_as_ushort(l1) << 16);
                *(unsigned*)(smx + pbase + jp * 4) = hv;
                *(unsigned*)(smx + pbase + 4608 + jp * 4) = lv;
            }
        }
        CP_WAIT0();
        __syncthreads();
        // mma: A = P [32 x 64], B = V [64c x 64j]
        {
            const unsigned PH = sb + A2_P, PL = PH + 4608;
            const unsigned VH = sb + A2_V, VL = VH + 9216;
            #pragma unroll
            for (int kt = 0; kt < 4; kt++) {
                const unsigned ka = (kt * 16 + ((lane >> 4) * 8)) * 2;
                const unsigned kb = (kt * 16 + (((lane >> 3) & 1) * 8)) * 2;
                unsigned ah[4], al[4];
                unsigned ao = (mB + (lane & 15)) * 144 + ka;
                ldsm4(ah, PH + ao);
                ldsm4(al, PL + ao);
                unsigned bh[4], bl[4];
                unsigned bo2 = (nB + (lane & 7) + ((lane >> 4) * 8)) * 144 + kb;
                ldsm4(bh, VH + bo2);
                ldsm4(bl, VL + bo2);
                mma16816(acc[0], ah, &bh[0]);
                mma16816(acc[1], ah, &bh[2]);
                mma16816(acc[0], ah, &bl[0]);
                mma16816(acc[1], ah, &bl[2]);
                mma16816(acc[0], al, &bh[0]);
                mma16816(acc[1], al, &bh[2]);
            }
        }
        __syncthreads();
    }
    ((float*)(smx + A2_LP))[w * 32 + lane] = lacc;
    __syncthreads();
    {
        const float* LP = (const float*)(smx + A2_LP);
        #pragma unroll
        for (int eh = 0; eh < 2; eh++) {
            int row = mB + (lane >> 2) + eh * 8;
            float lsum = 0.f;
            #pragma unroll
            for (int ww = 0; ww < 8; ww++) lsum += LP[ww * 32 + row];
            float inv = 1.f / lsum;
            #pragma unroll
            for (int nt = 0; nt < 2; nt++) {
                float v0 = acc[nt][eh * 2] * inv;
                float v1 = acc[nt][eh * 2 + 1] * inv;
                v0 = (v0 > 0.f) ? v0 : expm1f(v0);
                v1 = (v1 > 0.f) ? v1 : expm1f(v1);
                *(float2*)(out + (size_t)(i0 + row) * NCLASS + nB + nt * 8 + (lane & 3) * 2)
                    = make_float2(v0, v1);
            }
        }
    }
}

// K5: log_softmax
__global__ void logsoftmax_kernel(float* __restrict__ out) {
    int gw = (blockIdx.x * blockDim.x + threadIdx.x) >> 5;
    int lane = threadIdx.x & 31;
    if (gw >= N_NODES) return;
    float* row = out + (size_t)gw * NCLASS;
    float v1 = row[lane], v2 = row[lane + 32];
    float m = fmaxf(v1, v2);
    #pragma unroll
    for (int o = 16; o; o >>= 1) m = fmaxf(m, __shfl_xor_sync(~0u, m, o));
    float s = __expf(v1 - m) + __expf(v2 - m);
    #pragma unroll
    for (int o = 16; o; o >>= 1) s += __shfl_xor_sync(~0u, s, o);
    float ls = m + logf(s);
    row[lane] = v1 - ls;
    row[lane + 32] = v2 - ls;
}

extern "C" void kernel_launch(void* const* d_in, const int* in_sizes, int n_in,
                              void* d_out, int out_size) {
    const float* x   = (const float*)d_in[0];
    const int*   adj = (const int*)  d_in[1];
    const float* W   = (const float*)d_in[2];
    const float* a1  = (const float*)d_in[3];
    const float* a2  = (const float*)d_in[4];
    const float* Wo  = (const float*)d_in[5];
    const float* ao1 = (const float*)d_in[6];
    const float* ao2 = (const float*)d_in[7];
    float* out = (float*)d_out;

    cudaFuncSetAttribute(gat_attn1, cudaFuncAttributeMaxDynamicSharedMemorySize, SMEM_ATTN1);
    cudaFuncSetAttribute(wh_mma, cudaFuncAttributeMaxDynamicSharedMemorySize, WH_ST);

    bitpack_kernel<<<(N_NODES * N_NODES / 4) / 256, 256>>>(adj);
    xcvt_kernel<<<(N_NODES * NFEAT / 4) / 256, 256>>>(x);
    wcvt_kernel<<<(NHEADS * NHID * NFEAT) / 256, 256>>>(W);
    wh_mma<<<dim3(N_NODES / 128, NHEADS), 256, WH_ST>>>();
    whT_kernel<<<dim3(N_NODES / 64, NHID / 64, NHEADS), 256>>>();
    f12_kernel<<<(NHEADS * N_NODES) / 8, 256>>>(a1, a2);
    gat_attn1<<<dim3(N_NODES / 128, NHEADS), 256, SMEM_ATTN1>>>();
    who_gemm<<<dim3(N_NODES / 128, 4), 256>>>(Wo);
    g12_kernel<<<N_NODES / 8, 256>>>(ao1, ao2);
    whoT_kernel<<<N_NODES / 64, 256>>>();
    gat_attn2_mma<<<N_NODES / 32, 256>>>(out);
    logsoftmax_kernel<<<N_NODES / 8, 256>>>(out);
}